// round 1
// baseline (speedup 1.0000x reference)
#include <cuda_runtime.h>
#include <cuda_bf16.h>
#include <math.h>

// ---------------- Problem constants (fixed by setup_inputs) ----------------
#define BB 2
#define SS 13294
#define DD 256
#define NHH 8
#define HDD 32
#define LL 4
#define PP 4
#define FFF 1024
#define MM (BB * SS)           // 26588

// ---------------- Scratch (device globals; no allocation allowed) ----------
__device__ float g_v[(size_t)MM * DD];      // value proj, permuted (b,h,s,hd)
__device__ float g_off[(size_t)MM * DD];    // sampling offsets (m, 256)
__device__ float g_attn[(size_t)MM * 128];  // attention logits (m, 128)
__device__ float g_samp[(size_t)MM * DD];   // sampled output (m, 256)
__device__ float g_x[(size_t)MM * DD];      // after LN1
__device__ float g_h[(size_t)MM * FFF];     // FFN hidden

// ===========================================================================
// Generic 128x128x16 SGEMM: C[M,N] = A @ W + bias
//   ADDPOS: A := A + A2 (elementwise, fused into tile load)
//   RELU:   epilogue relu
//   PERMV:  store permuted for value tensor (b,h,s,hd)
// ===========================================================================
template <bool ADDPOS, bool RELU, bool PERMV>
__global__ void __launch_bounds__(256) gemm128(
    const float* __restrict__ A, const float* __restrict__ A2,
    const float* __restrict__ Wt, const float* __restrict__ bias,
    float* __restrict__ C, int Mdim, int Ndim, int Kdim)
{
    __shared__ float As[16][132];   // transposed A tile, padded
    __shared__ float Bs[16][128];

    const int tid = threadIdx.x;
    const int tx = tid & 15;
    const int ty = tid >> 4;
    const int m0 = blockIdx.y * 128;
    const int n0 = blockIdx.x * 128;

    float acc[8][8];
#pragma unroll
    for (int i = 0; i < 8; i++)
#pragma unroll
        for (int j = 0; j < 8; j++) acc[i][j] = 0.f;

    for (int k0 = 0; k0 < Kdim; k0 += 16) {
        // ---- load A tile (128 x 16), transposed into As ----
#pragma unroll
        for (int e = 0; e < 2; e++) {
            int fid = tid + 256 * e;
            int row = fid >> 2;
            int kq  = (fid & 3) * 4;
            int r = m0 + row; if (r >= Mdim) r = Mdim - 1;
            float4 v = *(const float4*)(A + (size_t)r * Kdim + k0 + kq);
            if (ADDPOS) {
                float4 v2 = *(const float4*)(A2 + (size_t)r * Kdim + k0 + kq);
                v.x += v2.x; v.y += v2.y; v.z += v2.z; v.w += v2.w;
            }
            As[kq + 0][row] = v.x;
            As[kq + 1][row] = v.y;
            As[kq + 2][row] = v.z;
            As[kq + 3][row] = v.w;
        }
        // ---- load B tile (16 x 128) ----
#pragma unroll
        for (int e = 0; e < 2; e++) {
            int fid = tid + 256 * e;
            int rr = fid >> 5;
            int cq = (fid & 31) * 4;
            *(float4*)&Bs[rr][cq] =
                *(const float4*)(Wt + (size_t)(k0 + rr) * Ndim + n0 + cq);
        }
        __syncthreads();

#pragma unroll
        for (int kk = 0; kk < 16; kk++) {
            float4 a0 = *(const float4*)&As[kk][ty * 4];
            float4 a1 = *(const float4*)&As[kk][64 + ty * 4];
            float4 b0 = *(const float4*)&Bs[kk][tx * 4];
            float4 b1 = *(const float4*)&Bs[kk][64 + tx * 4];
            float a[8] = {a0.x, a0.y, a0.z, a0.w, a1.x, a1.y, a1.z, a1.w};
            float b[8] = {b0.x, b0.y, b0.z, b0.w, b1.x, b1.y, b1.z, b1.w};
#pragma unroll
            for (int i = 0; i < 8; i++)
#pragma unroll
                for (int j = 0; j < 8; j++) acc[i][j] += a[i] * b[j];
        }
        __syncthreads();
    }

    // ---- epilogue ----
#pragma unroll
    for (int i = 0; i < 8; i++) {
        int r = m0 + ((i < 4) ? (ty * 4 + i) : (64 + ty * 4 + i - 4));
        if (r >= Mdim) continue;
        int bsel = (r >= SS) ? 1 : 0;          // B == 2
        int srow = r - bsel * SS;
#pragma unroll
        for (int j = 0; j < 8; j++) {
            int c = n0 + ((j < 4) ? (tx * 4 + j) : (64 + tx * 4 + j - 4));
            float val = acc[i][j] + bias[c];
            if (RELU) val = fmaxf(val, 0.f);
            if (PERMV) {
                int h = c >> 5, hd = c & 31;
                C[(((size_t)(bsel * NHH + h)) * SS + srow) * HDD + hd] = val;
            } else {
                C[(size_t)r * Ndim + c] = val;
            }
        }
    }
}

// ===========================================================================
// GEMM (BM=64, BN=256 full row) + bias + residual + LayerNorm epilogue.
// One block owns 64 complete rows -> LN via 16-lane shuffle reductions.
// ===========================================================================
__global__ void __launch_bounds__(256) gemm_ln(
    const float* __restrict__ A, const float* __restrict__ Wt,
    const float* __restrict__ bias, const float* __restrict__ resid,
    const float* __restrict__ gamma, const float* __restrict__ beta,
    float* __restrict__ C, int Mdim, int Kdim)
{
    __shared__ float As[16][68];    // transposed, padded
    __shared__ float Bs[16][256];

    const int tid = threadIdx.x;
    const int tx = tid & 15;
    const int ty = tid >> 4;
    const int m0 = blockIdx.x * 64;

    float acc[4][16];
#pragma unroll
    for (int i = 0; i < 4; i++)
#pragma unroll
        for (int j = 0; j < 16; j++) acc[i][j] = 0.f;

    for (int k0 = 0; k0 < Kdim; k0 += 16) {
        // A tile 64x16
        {
            int row = tid >> 2;
            int kq  = (tid & 3) * 4;
            int r = m0 + row; if (r >= Mdim) r = Mdim - 1;
            float4 v = *(const float4*)(A + (size_t)r * Kdim + k0 + kq);
            As[kq + 0][row] = v.x;
            As[kq + 1][row] = v.y;
            As[kq + 2][row] = v.z;
            As[kq + 3][row] = v.w;
        }
        // B tile 16x256
#pragma unroll
        for (int e = 0; e < 4; e++) {
            int fid = tid + 256 * e;
            int rr = fid >> 6;
            int cq = (fid & 63) * 4;
            *(float4*)&Bs[rr][cq] =
                *(const float4*)(Wt + (size_t)(k0 + rr) * DD + cq);
        }
        __syncthreads();

#pragma unroll
        for (int kk = 0; kk < 16; kk++) {
            float4 av = *(const float4*)&As[kk][ty * 4];
            float a[4] = {av.x, av.y, av.z, av.w};
#pragma unroll
            for (int g = 0; g < 4; g++) {
                float4 bv = *(const float4*)&Bs[kk][g * 64 + tx * 4];
                float b[4] = {bv.x, bv.y, bv.z, bv.w};
#pragma unroll
                for (int i = 0; i < 4; i++) {
#pragma unroll
                    for (int u = 0; u < 4; u++)
                        acc[i][g * 4 + u] += a[i] * b[u];
                }
            }
        }
        __syncthreads();
    }

    // ---- epilogue: bias + residual + LayerNorm ----
#pragma unroll
    for (int i = 0; i < 4; i++) {
        int r = m0 + ty * 4 + i;
        int rr = (r < Mdim) ? r : (Mdim - 1);
        // add bias + residual
#pragma unroll
        for (int g = 0; g < 4; g++)
#pragma unroll
            for (int u = 0; u < 4; u++) {
                int c = g * 64 + tx * 4 + u;
                acc[i][g * 4 + u] += bias[c] + resid[(size_t)rr * DD + c];
            }
        // mean (row spread over 16 lanes sharing ty)
        float s = 0.f;
#pragma unroll
        for (int j = 0; j < 16; j++) s += acc[i][j];
        s += __shfl_xor_sync(0xffffffffu, s, 1);
        s += __shfl_xor_sync(0xffffffffu, s, 2);
        s += __shfl_xor_sync(0xffffffffu, s, 4);
        s += __shfl_xor_sync(0xffffffffu, s, 8);
        float mean = s * (1.f / 256.f);
        float vs = 0.f;
#pragma unroll
        for (int j = 0; j < 16; j++) {
            float d = acc[i][j] - mean;
            vs += d * d;
        }
        vs += __shfl_xor_sync(0xffffffffu, vs, 1);
        vs += __shfl_xor_sync(0xffffffffu, vs, 2);
        vs += __shfl_xor_sync(0xffffffffu, vs, 4);
        vs += __shfl_xor_sync(0xffffffffu, vs, 8);
        float rstd = rsqrtf(vs * (1.f / 256.f) + 1e-5f);
        if (r < Mdim) {
#pragma unroll
            for (int g = 0; g < 4; g++)
#pragma unroll
                for (int u = 0; u < 4; u++) {
                    int c = g * 64 + tx * 4 + u;
                    C[(size_t)r * DD + c] =
                        (acc[i][g * 4 + u] - mean) * rstd * gamma[c] + beta[c];
                }
        }
    }
}

// ===========================================================================
// Deformable sampling: one warp per (b,h,s); lane = channel (HD=32).
// Softmax over 16 logits computed redundantly per lane (broadcast loads).
// ===========================================================================
__global__ void __launch_bounds__(256) sample_kernel(
    const float* __restrict__ vr)
{
    const int lvlW[4] = {100, 50, 25, 13};
    const int lvlH[4] = {100, 50, 25, 13};
    const int lvlStart[4] = {0, 10000, 12500, 13125};

    int warp = (blockIdx.x * blockDim.x + threadIdx.x) >> 5;
    int lane = threadIdx.x & 31;
    if (warp >= BB * NHH * SS) return;

    int b = warp / (NHH * SS);
    int rmn = warp - b * (NHH * SS);
    int h = rmn / SS;
    int s = rmn - h * SS;

    // query's own level + in-level coords
    int lq, jj;
    if (s < 10000)      { lq = 0; jj = s; }
    else if (s < 12500) { lq = 1; jj = s - 10000; }
    else if (s < 13125) { lq = 2; jj = s - 12500; }
    else                { lq = 3; jj = s - 13125; }
    int Wq = lvlW[lq], Hq = lvlH[lq];
    int yq = jj / Wq;
    int xq = jj - yq * Wq;
    float vrx = vr[(b * LL + lq) * 2 + 0];
    float vry = vr[(b * LL + lq) * 2 + 1];
    float refx = ((float)xq + 0.5f) / (vrx * (float)Wq);
    float refy = ((float)yq + 0.5f) / (vry * (float)Hq);

    size_t m = (size_t)b * SS + s;
    const float* offp = g_off + m * 256 + h * 32;
    const float* attp = g_attn + m * 128 + h * 16;

    // softmax over 16
    float logit[16];
    float mx = -1e30f;
#pragma unroll
    for (int t = 0; t < 16; t++) { logit[t] = attp[t]; mx = fmaxf(mx, logit[t]); }
    float se = 0.f;
#pragma unroll
    for (int t = 0; t < 16; t++) { logit[t] = __expf(logit[t] - mx); se += logit[t]; }
    float inv = 1.f / se;

    const float* vbase = g_v + ((size_t)(b * NHH + h)) * SS * HDD;
    float acc = 0.f;

#pragma unroll
    for (int lvl = 0; lvl < 4; lvl++) {
        const int Wl = lvlW[lvl], Hl = lvlH[lvl];
        const float* vl = vbase + (size_t)lvlStart[lvl] * HDD;
#pragma unroll
        for (int p = 0; p < 4; p++) {
            float w = logit[lvl * 4 + p] * inv;
            float ox = offp[lvl * 8 + p * 2 + 0];
            float oy = offp[lvl * 8 + p * 2 + 1];
            float locx = refx + ox / (float)Wl;
            float locy = refy + oy / (float)Hl;
            float x = locx * (float)Wl - 0.5f;
            float y = locy * (float)Hl - 0.5f;
            float x0f = floorf(x), y0f = floorf(y);
            float lx = x - x0f, ly = y - y0f;
            int x0 = (int)x0f, y0 = (int)y0f;
            int x1 = x0 + 1, y1 = y0 + 1;
            float w00 = (1.f - lx) * (1.f - ly);
            float w01 = lx * (1.f - ly);
            float w10 = (1.f - lx) * ly;
            float w11 = lx * ly;
            float sv = 0.f;
            bool x0ok = (x0 >= 0) & (x0 < Wl);
            bool x1ok = (x1 >= 0) & (x1 < Wl);
            if (y0 >= 0 && y0 < Hl) {
                if (x0ok) sv += w00 * vl[(size_t)(y0 * Wl + x0) * HDD + lane];
                if (x1ok) sv += w01 * vl[(size_t)(y0 * Wl + x1) * HDD + lane];
            }
            if (y1 >= 0 && y1 < Hl) {
                if (x0ok) sv += w10 * vl[(size_t)(y1 * Wl + x0) * HDD + lane];
                if (x1ok) sv += w11 * vl[(size_t)(y1 * Wl + x1) * HDD + lane];
            }
            acc += w * sv;
        }
    }
    g_samp[m * 256 + h * 32 + lane] = acc;
}

// ===========================================================================
// Launch
// ===========================================================================
extern "C" void kernel_launch(void* const* d_in, const int* in_sizes, int n_in,
                              void* d_out, int out_size)
{
    const float* query  = (const float*)d_in[0];
    const float* qpos   = (const float*)d_in[1];
    const float* vrat   = (const float*)d_in[2];
    // d_in[3] spatial_shapes (int64), d_in[4] level_start_index: fixed, hardcoded
    const float* W_off  = (const float*)d_in[5];
    const float* b_off  = (const float*)d_in[6];
    const float* W_attn = (const float*)d_in[7];
    const float* b_attn = (const float*)d_in[8];
    const float* W_val  = (const float*)d_in[9];
    const float* b_val  = (const float*)d_in[10];
    const float* W_out  = (const float*)d_in[11];
    const float* b_out  = (const float*)d_in[12];
    const float* ln1g   = (const float*)d_in[13];
    const float* ln1b   = (const float*)d_in[14];
    const float* W1     = (const float*)d_in[15];
    const float* b1     = (const float*)d_in[16];
    const float* W2     = (const float*)d_in[17];
    const float* b2     = (const float*)d_in[18];
    const float* ln2g   = (const float*)d_in[19];
    const float* ln2b   = (const float*)d_in[20];
    float* out = (float*)d_out;

    float *gv, *goff, *gattn, *gx, *gh;
    cudaGetSymbolAddress((void**)&gv,    g_v);
    cudaGetSymbolAddress((void**)&goff,  g_off);
    cudaGetSymbolAddress((void**)&gattn, g_attn);
    cudaGetSymbolAddress((void**)&gx,    g_x);
    cudaGetSymbolAddress((void**)&gh,    g_h);
    float* gsamp;
    cudaGetSymbolAddress((void**)&gsamp, g_samp);

    const int Mb128 = (MM + 127) / 128;   // 208
    const int Mb64  = (MM + 63) / 64;     // 416

    // value projection (permuted store into (b,h,s,hd))
    gemm128<false, false, true><<<dim3(DD / 128, Mb128), 256>>>(
        query, nullptr, W_val, b_val, gv, MM, DD, DD);
    // sampling offsets: (query + pos) @ W_off
    gemm128<true, false, false><<<dim3(DD / 128, Mb128), 256>>>(
        query, qpos, W_off, b_off, goff, MM, DD, DD);
    // attention logits: (query + pos) @ W_attn
    gemm128<true, false, false><<<dim3(128 / 128, Mb128), 256>>>(
        query, qpos, W_attn, b_attn, gattn, MM, 128, DD);
    // deformable sampling (softmax fused)
    sample_kernel<<<(BB * NHH * SS) / 8, 256>>>(vrat);
    // output projection + residual(query) + LN1 -> x
    gemm_ln<<<Mb64, 256>>>(gsamp, W_out, b_out, query, ln1g, ln1b, gx, MM, DD);
    // FFN up + relu
    gemm128<false, true, false><<<dim3(FFF / 128, Mb128), 256>>>(
        gx, nullptr, W1, b1, gh, MM, FFF, DD);
    // FFN down + residual(x) + LN2 -> out
    gemm_ln<<<Mb64, 256>>>(gh, W2, b2, gx, ln2g, ln2b, out, MM, FFF);
    (void)in_sizes; (void)n_in; (void)out_size;
}

// round 5
// speedup vs baseline: 2.0013x; 2.0013x over previous
#include <cuda_runtime.h>
#include <cuda_bf16.h>
#include <math.h>
#include <stdint.h>

// ---------------- Problem constants ----------------
#define BB 2
#define SS 13294
#define DD 256
#define FFF 1024
#define MM (BB * SS)   // 26588

// ---------------- Scratch (device globals) ----------------
__device__ __nv_bfloat16 g_qh[(size_t)MM * DD], g_ql[(size_t)MM * DD];
__device__ __nv_bfloat16 g_qph[(size_t)MM * DD], g_qpl[(size_t)MM * DD];
__device__ float g_v[(size_t)MM * DD];
__device__ float g_off[(size_t)MM * DD];
__device__ float g_attn[(size_t)MM * 128];
__device__ __nv_bfloat16 g_sh[(size_t)MM * DD], g_sl[(size_t)MM * DD];
__device__ float g_ao[(size_t)MM * DD];
__device__ float g_x[(size_t)MM * DD];
__device__ __nv_bfloat16 g_xh[(size_t)MM * DD], g_xl[(size_t)MM * DD];
__device__ __nv_bfloat16 g_hh[(size_t)MM * FFF], g_hl[(size_t)MM * FFF];
__device__ float g_f[(size_t)MM * DD];
// weights transposed + split: [N][K] bf16 hi/lo
__device__ __nv_bfloat16 w_v_h[DD * DD],  w_v_l[DD * DD];
__device__ __nv_bfloat16 w_o_h[DD * DD],  w_o_l[DD * DD];
__device__ __nv_bfloat16 w_a_h[128 * DD], w_a_l[128 * DD];
__device__ __nv_bfloat16 w_u_h[DD * DD],  w_u_l[DD * DD];
__device__ __nv_bfloat16 w_1_h[FFF * DD], w_1_l[FFF * DD];
__device__ __nv_bfloat16 w_2_h[DD * FFF], w_2_l[DD * FFF];

// ---------------- helpers ----------------
__device__ __forceinline__ uint32_t smem_u32(const void* p) {
    uint32_t a;
    asm("{ .reg .u64 t; cvta.to.shared.u64 t, %1; cvt.u32.u64 %0, t; }"
        : "=r"(a) : "l"(p));
    return a;
}
__device__ __forceinline__ void cp16(uint32_t dst, const void* src) {
    asm volatile("cp.async.cg.shared.global [%0], [%1], 16;"
                 :: "r"(dst), "l"(src) : "memory");
}
__device__ __forceinline__ void cp_commit() {
    asm volatile("cp.async.commit_group;" ::: "memory");
}
__device__ __forceinline__ void splitf(float v, __nv_bfloat16& h, __nv_bfloat16& l) {
    h = __float2bfloat16_rn(v);
    l = __float2bfloat16_rn(v - __bfloat162float(h));
}
__device__ __forceinline__ void store_pair(__nv_bfloat16* p, __nv_bfloat16 a, __nv_bfloat16 b) {
    *(__nv_bfloat162*)p = __halves2bfloat162(a, b);
}
__device__ __forceinline__ void hmma(float* c, const uint32_t* a, const uint32_t* b) {
    asm volatile(
        "mma.sync.aligned.m16n8k16.row.col.f32.bf16.bf16.f32 "
        "{%0,%1,%2,%3}, {%4,%5,%6,%7}, {%8,%9}, {%0,%1,%2,%3};"
        : "+f"(c[0]), "+f"(c[1]), "+f"(c[2]), "+f"(c[3])
        : "r"(a[0]), "r"(a[1]), "r"(a[2]), "r"(a[3]), "r"(b[0]), "r"(b[1]));
}

// ===========================================================================
// Weight transpose + split: src [K][N] f32 -> dst_h/dst_l [N][K] bf16
// ===========================================================================
__global__ void __launch_bounds__(256) wsplit_kernel(
    const float* __restrict__ src, __nv_bfloat16* __restrict__ dh,
    __nv_bfloat16* __restrict__ dl, int K, int N)
{
    int i = blockIdx.x * 256 + threadIdx.x;
    if (i >= K * N) return;
    int k = i / N, n = i - k * N;
    __nv_bfloat16 h, l;
    splitf(src[i], h, l);
    dh[(size_t)n * K + k] = h;
    dl[(size_t)n * K + k] = l;
}

// ===========================================================================
// query / query+pos split
// ===========================================================================
__global__ void __launch_bounds__(256) splitq_kernel(
    const float* __restrict__ Q, const float* __restrict__ P)
{
    int i = blockIdx.x * 256 + threadIdx.x;   // one float4 per thread
    if (i >= MM * (DD / 4)) return;
    float4 q = ((const float4*)Q)[i];
    float4 p = ((const float4*)P)[i];
    size_t o = (size_t)i * 4;
    __nv_bfloat16 h0, l0, h1, l1, h2, l2, h3, l3;
    splitf(q.x, h0, l0); splitf(q.y, h1, l1); splitf(q.z, h2, l2); splitf(q.w, h3, l3);
    store_pair(g_qh + o, h0, h1); store_pair(g_qh + o + 2, h2, h3);
    store_pair(g_ql + o, l0, l1); store_pair(g_ql + o + 2, l2, l3);
    float4 s = make_float4(q.x + p.x, q.y + p.y, q.z + p.z, q.w + p.w);
    splitf(s.x, h0, l0); splitf(s.y, h1, l1); splitf(s.z, h2, l2); splitf(s.w, h3, l3);
    store_pair(g_qph + o, h0, h1); store_pair(g_qph + o + 2, h2, h3);
    store_pair(g_qpl + o, l0, l1); store_pair(g_qpl + o + 2, l2, l3);
}

// ===========================================================================
// mma.sync bf16-split GEMM: C = A @ B^T + bias
//   A[M,K] hi/lo bf16 row-major, B[N,K] hi/lo bf16 row-major.
//   3-pass compensated: ah*bh + ah*bl + al*bh
//   MODE 0: f32 +bias -> Cf[M,N]
//   MODE 1: f32 +bias -> value layout (b,h,s,hd)
//   MODE 2: relu(.+bias) -> bf16 hi/lo split Chi/Clo
// CTA tile 128x128, BK=32, 8 warps (4x2), warp tile 32x64.
// ===========================================================================
#define KSTR 40                         // padded row stride (bf16 elems)
#define TEN_B (128 * KSTR * 2)          // bytes per tensor tile = 10240
#define BUF_B (4 * TEN_B)               // Ah,Al,Bh,Bl  = 40960
#define GEMM_SMEM (2 * BUF_B)           // 81920

template <int MODE>
__global__ void __launch_bounds__(256) mma_gemm(
    const __nv_bfloat16* __restrict__ Ah, const __nv_bfloat16* __restrict__ Al,
    const __nv_bfloat16* __restrict__ Bh, const __nv_bfloat16* __restrict__ Bl,
    const float* __restrict__ bias,
    float* __restrict__ Cf, __nv_bfloat16* __restrict__ Chi,
    __nv_bfloat16* __restrict__ Clo,
    int Mdim, int Ndim, int Kdim)
{
    extern __shared__ char smem[];
    const uint32_t sb = smem_u32(smem);
    const int tid = threadIdx.x;
    const int wid = tid >> 5;
    const int lane = tid & 31;
    const int wm = wid & 3;             // warp row 0..3  (32 rows each)
    const int wn = wid >> 2;            // warp col 0..1  (64 cols each)
    const int m0 = blockIdx.y * 128;
    const int n0 = blockIdx.x * 128;
    const int NC = Kdim >> 5;           // K chunks of 32

    const int l4 = lane >> 2;           // 0..7
    const int t4 = lane & 3;            // 0..3

    float acc[2][8][4];
#pragma unroll
    for (int i = 0; i < 2; i++)
#pragma unroll
        for (int j = 0; j < 8; j++)
#pragma unroll
            for (int q = 0; q < 4; q++) acc[i][j][q] = 0.f;

    // ---- tile loader ----
    auto load_chunk = [&](int kc) {
        const int b = kc & 1;
        const int k0 = kc * 32;
        const uint32_t bufb = sb + b * BUF_B;
#pragma unroll
        for (int t = 0; t < 4; t++) {
            const __nv_bfloat16* src = (t == 0) ? Ah : (t == 1) ? Al : (t == 2) ? Bh : Bl;
            const int rb = (t < 2) ? m0 : n0;
#pragma unroll
            for (int e = 0; e < 2; e++) {
                int u = tid + e * 256;
                int r = u >> 2;
                int g = u & 3;
                int gr = rb + r;
                if (t < 2) { if (gr >= Mdim) gr = Mdim - 1; }
                cp16(bufb + (uint32_t)t * TEN_B + (uint32_t)(r * KSTR + g * 8) * 2,
                     src + (size_t)gr * Kdim + k0 + g * 8);
            }
        }
        cp_commit();
    };

    load_chunk(0);

    for (int kc = 0; kc < NC; kc++) {
        if (kc + 1 < NC) {
            load_chunk(kc + 1);
            asm volatile("cp.async.wait_group 1;" ::: "memory");
        } else {
            asm volatile("cp.async.wait_group 0;" ::: "memory");
        }
        __syncthreads();

        const char* buf = smem + (kc & 1) * BUF_B;
        const char* pAh = buf;
        const char* pAl = buf + TEN_B;
        const char* pBh = buf + 2 * TEN_B;
        const char* pBl = buf + 3 * TEN_B;

#pragma unroll
        for (int ks = 0; ks < 2; ks++) {
            const int kk = ks * 16 + t4 * 2;
            uint32_t afh[2][4], afl[2][4];
#pragma unroll
            for (int mt = 0; mt < 2; mt++) {
                int r0 = wm * 32 + mt * 16 + l4;
                afh[mt][0] = *(const uint32_t*)(pAh + (r0 * KSTR + kk) * 2);
                afh[mt][1] = *(const uint32_t*)(pAh + ((r0 + 8) * KSTR + kk) * 2);
                afh[mt][2] = *(const uint32_t*)(pAh + (r0 * KSTR + kk + 8) * 2);
                afh[mt][3] = *(const uint32_t*)(pAh + ((r0 + 8) * KSTR + kk + 8) * 2);
                afl[mt][0] = *(const uint32_t*)(pAl + (r0 * KSTR + kk) * 2);
                afl[mt][1] = *(const uint32_t*)(pAl + ((r0 + 8) * KSTR + kk) * 2);
                afl[mt][2] = *(const uint32_t*)(pAl + (r0 * KSTR + kk + 8) * 2);
                afl[mt][3] = *(const uint32_t*)(pAl + ((r0 + 8) * KSTR + kk + 8) * 2);
            }
#pragma unroll
            for (int nt = 0; nt < 8; nt++) {
                int n = wn * 64 + nt * 8 + l4;
                uint32_t bfh[2], bfl[2];
                bfh[0] = *(const uint32_t*)(pBh + (n * KSTR + kk) * 2);
                bfh[1] = *(const uint32_t*)(pBh + (n * KSTR + kk + 8) * 2);
                bfl[0] = *(const uint32_t*)(pBl + (n * KSTR + kk) * 2);
                bfl[1] = *(const uint32_t*)(pBl + (n * KSTR + kk + 8) * 2);
#pragma unroll
                for (int mt = 0; mt < 2; mt++) {
                    hmma(acc[mt][nt], afh[mt], bfh);
                    hmma(acc[mt][nt], afh[mt], bfl);
                    hmma(acc[mt][nt], afl[mt], bfh);
                }
            }
        }
        __syncthreads();
    }

    // ---- epilogue from register fragments ----
#pragma unroll
    for (int mt = 0; mt < 2; mt++) {
        int r0 = m0 + wm * 32 + mt * 16 + l4;
#pragma unroll
        for (int half = 0; half < 2; half++) {
            int r = r0 + half * 8;
            if (r >= Mdim) continue;
            int bsel = (r >= SS) ? 1 : 0;
            int s = r - bsel * SS;
#pragma unroll
            for (int nt = 0; nt < 8; nt++) {
                int c = n0 + wn * 64 + nt * 8 + t4 * 2;
                float v0 = acc[mt][nt][half * 2 + 0] + bias[c];
                float v1 = acc[mt][nt][half * 2 + 1] + bias[c + 1];
                if (MODE == 0) {
                    *(float2*)(Cf + (size_t)r * Ndim + c) = make_float2(v0, v1);
                } else if (MODE == 1) {
                    int h = c >> 5, hd = c & 31;
                    *(float2*)(Cf + (((size_t)(bsel * 8 + h)) * SS + s) * 32 + hd) =
                        make_float2(v0, v1);
                } else {
                    v0 = fmaxf(v0, 0.f);
                    v1 = fmaxf(v1, 0.f);
                    __nv_bfloat16 h0, l0, h1, l1;
                    splitf(v0, h0, l0); splitf(v1, h1, l1);
                    store_pair(Chi + (size_t)r * Ndim + c, h0, h1);
                    store_pair(Clo + (size_t)r * Ndim + c, l0, l1);
                }
            }
        }
    }
}

// ===========================================================================
// Deformable sampling: 8 lanes per (b,s,h), float4 channels per lane.
// Writes bf16 hi/lo split for the out-projection GEMM.
// ===========================================================================
__global__ void __launch_bounds__(256) sample_kernel(const float* __restrict__ vr)
{
    const int lvlW[4] = {100, 50, 25, 13};
    const int lvlS[4] = {0, 10000, 12500, 13125};

    int gw = (blockIdx.x * 256 + threadIdx.x) >> 5;
    int lane = threadIdx.x & 31;
    int m = gw >> 1;
    if (m >= MM) return;
    int hq = ((gw & 1) << 2) + (lane >> 3);
    int c0 = (lane & 7) << 2;

    int b = (m >= SS) ? 1 : 0;
    int s = m - b * SS;
    int lq, jj;
    if (s < 10000)      { lq = 0; jj = s; }
    else if (s < 12500) { lq = 1; jj = s - 10000; }
    else if (s < 13125) { lq = 2; jj = s - 12500; }
    else                { lq = 3; jj = s - 13125; }
    int Wq = lvlW[lq];
    int yq = jj / Wq, xq = jj - yq * Wq;
    float vrx = vr[(b * 4 + lq) * 2 + 0];
    float vry = vr[(b * 4 + lq) * 2 + 1];
    float refx = ((float)xq + 0.5f) / (vrx * (float)Wq);
    float refy = ((float)yq + 0.5f) / (vry * (float)Wq);

    const float* attp = g_attn + (size_t)m * 128 + hq * 16;
    float logit[16];
    float mx = -1e30f;
#pragma unroll
    for (int t = 0; t < 4; t++) {
        float4 a4 = *(const float4*)(attp + t * 4);
        logit[t * 4 + 0] = a4.x; logit[t * 4 + 1] = a4.y;
        logit[t * 4 + 2] = a4.z; logit[t * 4 + 3] = a4.w;
    }
#pragma unroll
    for (int t = 0; t < 16; t++) mx = fmaxf(mx, logit[t]);
    float se = 0.f;
#pragma unroll
    for (int t = 0; t < 16; t++) { logit[t] = __expf(logit[t] - mx); se += logit[t]; }
    float inv = 1.f / se;

    const float* offp = g_off + (size_t)m * 256 + hq * 32;
    float ax = 0.f, ay = 0.f, az = 0.f, aw = 0.f;

#pragma unroll
    for (int lvl = 0; lvl < 4; lvl++) {
        const int Wl = lvlW[lvl];
        const float* vplane = g_v + (((size_t)(b * 8 + hq)) * SS + lvlS[lvl]) * 32 + c0;
        float fx = refx * (float)Wl - 0.5f;
        float fy = refy * (float)Wl - 0.5f;
        float4 o0 = *(const float4*)(offp + lvl * 8);
        float4 o1 = *(const float4*)(offp + lvl * 8 + 4);
        float oxs[4] = {o0.x, o0.z, o1.x, o1.z};
        float oys[4] = {o0.y, o0.w, o1.y, o1.w};
#pragma unroll
        for (int p = 0; p < 4; p++) {
            float w = logit[lvl * 4 + p];
            float x = fx + oxs[p];
            float y = fy + oys[p];
            float x0f = floorf(x), y0f = floorf(y);
            float lx = x - x0f, ly = y - y0f;
            int x0 = (int)x0f, y0 = (int)y0f;
            bool x0ok = ((unsigned)x0 < (unsigned)Wl);
            bool x1ok = ((unsigned)(x0 + 1) < (unsigned)Wl);
            float w00 = w * (1.f - lx) * (1.f - ly);
            float w01 = w * lx * (1.f - ly);
            float w10 = w * (1.f - lx) * ly;
            float w11 = w * lx * ly;
            if ((unsigned)y0 < (unsigned)Wl) {
                const float* rp = vplane + (size_t)(y0 * Wl) * 32;
                if (x0ok) {
                    float4 v = *(const float4*)(rp + (size_t)x0 * 32);
                    ax = fmaf(w00, v.x, ax); ay = fmaf(w00, v.y, ay);
                    az = fmaf(w00, v.z, az); aw = fmaf(w00, v.w, aw);
                }
                if (x1ok) {
                    float4 v = *(const float4*)(rp + (size_t)(x0 + 1) * 32);
                    ax = fmaf(w01, v.x, ax); ay = fmaf(w01, v.y, ay);
                    az = fmaf(w01, v.z, az); aw = fmaf(w01, v.w, aw);
                }
            }
            if ((unsigned)(y0 + 1) < (unsigned)Wl) {
                const float* rp = vplane + (size_t)((y0 + 1) * Wl) * 32;
                if (x0ok) {
                    float4 v = *(const float4*)(rp + (size_t)x0 * 32);
                    ax = fmaf(w10, v.x, ax); ay = fmaf(w10, v.y, ay);
                    az = fmaf(w10, v.z, az); aw = fmaf(w10, v.w, aw);
                }
                if (x1ok) {
                    float4 v = *(const float4*)(rp + (size_t)(x0 + 1) * 32);
                    ax = fmaf(w11, v.x, ax); ay = fmaf(w11, v.y, ay);
                    az = fmaf(w11, v.z, az); aw = fmaf(w11, v.w, aw);
                }
            }
        }
    }
    ax *= inv; ay *= inv; az *= inv; aw *= inv;

    size_t ob = (size_t)m * 256 + hq * 32 + c0;
    __nv_bfloat16 h0, l0, h1, l1, h2, l2, h3, l3;
    splitf(ax, h0, l0); splitf(ay, h1, l1); splitf(az, h2, l2); splitf(aw, h3, l3);
    store_pair(g_sh + ob, h0, h1); store_pair(g_sh + ob + 2, h2, h3);
    store_pair(g_sl + ob, l0, l1); store_pair(g_sl + ob + 2, l2, l3);
}

// ===========================================================================
// Row LayerNorm: X = LN(A + R); optionally also write bf16 hi/lo split.
// ===========================================================================
template <bool WB>
__global__ void __launch_bounds__(256) ln_kernel(
    const float* __restrict__ A, const float* __restrict__ R,
    const float* __restrict__ gam, const float* __restrict__ bet,
    float* __restrict__ Xf, __nv_bfloat16* __restrict__ Xh,
    __nv_bfloat16* __restrict__ Xl)
{
    int row = blockIdx.x * 8 + (threadIdx.x >> 5);
    if (row >= MM) return;
    int lane = threadIdx.x & 31;
    const float4* pa = (const float4*)(A + (size_t)row * 256);
    const float4* pr = (const float4*)(R + (size_t)row * 256);
    float4 v0 = pa[lane],      r0 = pr[lane];
    float4 v1 = pa[lane + 32], r1 = pr[lane + 32];
    v0.x += r0.x; v0.y += r0.y; v0.z += r0.z; v0.w += r0.w;
    v1.x += r1.x; v1.y += r1.y; v1.z += r1.z; v1.w += r1.w;

    float s = v0.x + v0.y + v0.z + v0.w + v1.x + v1.y + v1.z + v1.w;
#pragma unroll
    for (int d = 1; d < 32; d <<= 1) s += __shfl_xor_sync(0xffffffffu, s, d);
    float mean = s * (1.f / 256.f);
    float vs =
        (v0.x - mean) * (v0.x - mean) + (v0.y - mean) * (v0.y - mean) +
        (v0.z - mean) * (v0.z - mean) + (v0.w - mean) * (v0.w - mean) +
        (v1.x - mean) * (v1.x - mean) + (v1.y - mean) * (v1.y - mean) +
        (v1.z - mean) * (v1.z - mean) + (v1.w - mean) * (v1.w - mean);
#pragma unroll
    for (int d = 1; d < 32; d <<= 1) vs += __shfl_xor_sync(0xffffffffu, vs, d);
    float rstd = rsqrtf(vs * (1.f / 256.f) + 1e-5f);

    float4 g0 = ((const float4*)gam)[lane], g1 = ((const float4*)gam)[lane + 32];
    float4 b0 = ((const float4*)bet)[lane], b1 = ((const float4*)bet)[lane + 32];
    float4 o0, o1;
    o0.x = (v0.x - mean) * rstd * g0.x + b0.x;
    o0.y = (v0.y - mean) * rstd * g0.y + b0.y;
    o0.z = (v0.z - mean) * rstd * g0.z + b0.z;
    o0.w = (v0.w - mean) * rstd * g0.w + b0.w;
    o1.x = (v1.x - mean) * rstd * g1.x + b1.x;
    o1.y = (v1.y - mean) * rstd * g1.y + b1.y;
    o1.z = (v1.z - mean) * rstd * g1.z + b1.z;
    o1.w = (v1.w - mean) * rstd * g1.w + b1.w;
    ((float4*)(Xf + (size_t)row * 256))[lane] = o0;
    ((float4*)(Xf + (size_t)row * 256))[lane + 32] = o1;

    if (WB) {
        size_t ob = (size_t)row * 256 + lane * 4;
        __nv_bfloat16 h0, l0, h1, l1, h2, l2, h3, l3;
        splitf(o0.x, h0, l0); splitf(o0.y, h1, l1); splitf(o0.z, h2, l2); splitf(o0.w, h3, l3);
        store_pair(Xh + ob, h0, h1); store_pair(Xh + ob + 2, h2, h3);
        store_pair(Xl + ob, l0, l1); store_pair(Xl + ob + 2, l2, l3);
        ob += 128;
        splitf(o1.x, h0, l0); splitf(o1.y, h1, l1); splitf(o1.z, h2, l2); splitf(o1.w, h3, l3);
        store_pair(Xh + ob, h0, h1); store_pair(Xh + ob + 2, h2, h3);
        store_pair(Xl + ob, l0, l1); store_pair(Xl + ob + 2, l2, l3);
    }
}

// ===========================================================================
// Launch
// ===========================================================================
extern "C" void kernel_launch(void* const* d_in, const int* in_sizes, int n_in,
                              void* d_out, int out_size)
{
    const float* query  = (const float*)d_in[0];
    const float* qpos   = (const float*)d_in[1];
    const float* vrat   = (const float*)d_in[2];
    const float* W_off  = (const float*)d_in[5];
    const float* b_off  = (const float*)d_in[6];
    const float* W_attn = (const float*)d_in[7];
    const float* b_attn = (const float*)d_in[8];
    const float* W_val  = (const float*)d_in[9];
    const float* b_val  = (const float*)d_in[10];
    const float* W_out  = (const float*)d_in[11];
    const float* b_out  = (const float*)d_in[12];
    const float* ln1g   = (const float*)d_in[13];
    const float* ln1b   = (const float*)d_in[14];
    const float* W1     = (const float*)d_in[15];
    const float* b1     = (const float*)d_in[16];
    const float* W2     = (const float*)d_in[17];
    const float* b2     = (const float*)d_in[18];
    const float* ln2g   = (const float*)d_in[19];
    const float* ln2b   = (const float*)d_in[20];
    float* out = (float*)d_out;

    void *p_qh, *p_ql, *p_qph, *p_qpl, *p_v, *p_off, *p_attn, *p_sh, *p_sl;
    void *p_ao, *p_x, *p_xh, *p_xl, *p_hh, *p_hl, *p_f;
    void *pwvh, *pwvl, *pwoh, *pwol, *pwah, *pwal, *pwuh, *pwul, *pw1h, *pw1l, *pw2h, *pw2l;
    cudaGetSymbolAddress(&p_qh, g_qh);   cudaGetSymbolAddress(&p_ql, g_ql);
    cudaGetSymbolAddress(&p_qph, g_qph); cudaGetSymbolAddress(&p_qpl, g_qpl);
    cudaGetSymbolAddress(&p_v, g_v);     cudaGetSymbolAddress(&p_off, g_off);
    cudaGetSymbolAddress(&p_attn, g_attn);
    cudaGetSymbolAddress(&p_sh, g_sh);   cudaGetSymbolAddress(&p_sl, g_sl);
    cudaGetSymbolAddress(&p_ao, g_ao);   cudaGetSymbolAddress(&p_x, g_x);
    cudaGetSymbolAddress(&p_xh, g_xh);   cudaGetSymbolAddress(&p_xl, g_xl);
    cudaGetSymbolAddress(&p_hh, g_hh);   cudaGetSymbolAddress(&p_hl, g_hl);
    cudaGetSymbolAddress(&p_f, g_f);
    cudaGetSymbolAddress(&pwvh, w_v_h); cudaGetSymbolAddress(&pwvl, w_v_l);
    cudaGetSymbolAddress(&pwoh, w_o_h); cudaGetSymbolAddress(&pwol, w_o_l);
    cudaGetSymbolAddress(&pwah, w_a_h); cudaGetSymbolAddress(&pwal, w_a_l);
    cudaGetSymbolAddress(&pwuh, w_u_h); cudaGetSymbolAddress(&pwul, w_u_l);
    cudaGetSymbolAddress(&pw1h, w_1_h); cudaGetSymbolAddress(&pw1l, w_1_l);
    cudaGetSymbolAddress(&pw2h, w_2_h); cudaGetSymbolAddress(&pw2l, w_2_l);

    cudaFuncSetAttribute(mma_gemm<0>, cudaFuncAttributeMaxDynamicSharedMemorySize, GEMM_SMEM);
    cudaFuncSetAttribute(mma_gemm<1>, cudaFuncAttributeMaxDynamicSharedMemorySize, GEMM_SMEM);
    cudaFuncSetAttribute(mma_gemm<2>, cudaFuncAttributeMaxDynamicSharedMemorySize, GEMM_SMEM);

    // --- weight prep ---
    wsplit_kernel<<<(DD * DD + 255) / 256, 256>>>(W_val, (__nv_bfloat16*)pwvh, (__nv_bfloat16*)pwvl, DD, DD);
    wsplit_kernel<<<(DD * DD + 255) / 256, 256>>>(W_off, (__nv_bfloat16*)pwoh, (__nv_bfloat16*)pwol, DD, DD);
    wsplit_kernel<<<(DD * 128 + 255) / 256, 256>>>(W_attn, (__nv_bfloat16*)pwah, (__nv_bfloat16*)pwal, DD, 128);
    wsplit_kernel<<<(DD * DD + 255) / 256, 256>>>(W_out, (__nv_bfloat16*)pwuh, (__nv_bfloat16*)pwul, DD, DD);
    wsplit_kernel<<<(DD * FFF + 255) / 256, 256>>>(W1, (__nv_bfloat16*)pw1h, (__nv_bfloat16*)pw1l, DD, FFF);
    wsplit_kernel<<<(FFF * DD + 255) / 256, 256>>>(W2, (__nv_bfloat16*)pw2h, (__nv_bfloat16*)pw2l, FFF, DD);

    // --- activation split ---
    splitq_kernel<<<(MM * (DD / 4) + 255) / 256, 256>>>(query, qpos);

    const int MT = (MM + 127) / 128;   // 208

    // value projection -> g_v (permuted)
    mma_gemm<1><<<dim3(2, MT), 256, GEMM_SMEM>>>(
        (const __nv_bfloat16*)p_qh, (const __nv_bfloat16*)p_ql,
        (const __nv_bfloat16*)pwvh, (const __nv_bfloat16*)pwvl,
        b_val, (float*)p_v, nullptr, nullptr, MM, DD, DD);
    // offsets
    mma_gemm<0><<<dim3(2, MT), 256, GEMM_SMEM>>>(
        (const __nv_bfloat16*)p_qph, (const __nv_bfloat16*)p_qpl,
        (const __nv_bfloat16*)pwoh, (const __nv_bfloat16*)pwol,
        b_off, (float*)p_off, nullptr, nullptr, MM, DD, DD);
    // attention logits
    mma_gemm<0><<<dim3(1, MT), 256, GEMM_SMEM>>>(
        (const __nv_bfloat16*)p_qph, (const __nv_bfloat16*)p_qpl,
        (const __nv_bfloat16*)pwah, (const __nv_bfloat16*)pwal,
        b_attn, (float*)p_attn, nullptr, nullptr, MM, 128, DD);
    // sampling (writes g_sh/g_sl)
    sample_kernel<<<(MM * 8 + 31) / 32, 256>>>(vrat);
    // out projection -> g_ao
    mma_gemm<0><<<dim3(2, MT), 256, GEMM_SMEM>>>(
        (const __nv_bfloat16*)p_sh, (const __nv_bfloat16*)p_sl,
        (const __nv_bfloat16*)pwuh, (const __nv_bfloat16*)pwul,
        b_out, (float*)p_ao, nullptr, nullptr, MM, DD, DD);
    // LN1: x = LN(query + attn_out), also bf16 split
    ln_kernel<true><<<(MM + 7) / 8, 256>>>(
        (const float*)p_ao, query, ln1g, ln1b,
        (float*)p_x, (__nv_bfloat16*)p_xh, (__nv_bfloat16*)p_xl);
    // FFN up + relu -> h (bf16 split)
    mma_gemm<2><<<dim3(8, MT), 256, GEMM_SMEM>>>(
        (const __nv_bfloat16*)p_xh, (const __nv_bfloat16*)p_xl,
        (const __nv_bfloat16*)pw1h, (const __nv_bfloat16*)pw1l,
        b1, nullptr, (__nv_bfloat16*)p_hh, (__nv_bfloat16*)p_hl, MM, FFF, DD);
    // FFN down -> g_f
    mma_gemm<0><<<dim3(2, MT), 256, GEMM_SMEM>>>(
        (const __nv_bfloat16*)p_hh, (const __nv_bfloat16*)p_hl,
        (const __nv_bfloat16*)pw2h, (const __nv_bfloat16*)pw2l,
        b2, (float*)p_f, nullptr, nullptr, MM, DD, FFF);
    // LN2 -> out
    ln_kernel<false><<<(MM + 7) / 8, 256>>>(
        (const float*)p_f, (const float*)p_x, ln2g, ln2b,
        out, nullptr, nullptr);

    (void)in_sizes; (void)n_in; (void)out_size;
}

// round 9
// speedup vs baseline: 2.2815x; 1.1400x over previous
#include <cuda_runtime.h>
#include <cuda_bf16.h>
#include <math.h>
#include <stdint.h>

// ---------------- Problem constants ----------------
#define BB 2
#define SS 13294
#define DD 256
#define FFF 1024
#define MM (BB * SS)   // 26588

// ---------------- Scratch (device globals) ----------------
__device__ __nv_bfloat16 g_qh[(size_t)MM * DD], g_ql[(size_t)MM * DD];
__device__ __nv_bfloat16 g_qph[(size_t)MM * DD], g_qpl[(size_t)MM * DD];
__device__ float g_v[(size_t)MM * DD];
__device__ float g_off[(size_t)MM * DD];
__device__ float g_attn[(size_t)MM * 128];
__device__ __nv_bfloat16 g_sh[(size_t)MM * DD], g_sl[(size_t)MM * DD];
__device__ float g_ao[(size_t)MM * DD];
__device__ float g_x[(size_t)MM * DD];
__device__ __nv_bfloat16 g_xh[(size_t)MM * DD], g_xl[(size_t)MM * DD];
__device__ __nv_bfloat16 g_hh[(size_t)MM * FFF], g_hl[(size_t)MM * FFF];
__device__ float g_f[(size_t)MM * DD];
// weights transposed + split: [N][K] bf16 hi/lo
__device__ __nv_bfloat16 w_v_h[DD * DD],   w_v_l[DD * DD];
__device__ __nv_bfloat16 w_oa_h[384 * DD], w_oa_l[384 * DD];   // off(0-255) + attn(256-383)
__device__ __nv_bfloat16 w_u_h[DD * DD],   w_u_l[DD * DD];
__device__ __nv_bfloat16 w_1_h[FFF * DD],  w_1_l[FFF * DD];
__device__ __nv_bfloat16 w_2_h[DD * FFF],  w_2_l[DD * FFF];
__device__ float g_boa[384];

// ---------------- helpers ----------------
__device__ __forceinline__ uint32_t smem_u32(const void* p) {
    uint32_t a;
    asm("{ .reg .u64 t; cvta.to.shared.u64 t, %1; cvt.u32.u64 %0, t; }"
        : "=r"(a) : "l"(p));
    return a;
}
__device__ __forceinline__ void cp16(uint32_t dst, const void* src) {
    asm volatile("cp.async.cg.shared.global [%0], [%1], 16;"
                 :: "r"(dst), "l"(src) : "memory");
}
__device__ __forceinline__ void cp_commit() {
    asm volatile("cp.async.commit_group;" ::: "memory");
}
__device__ __forceinline__ void splitf(float v, __nv_bfloat16& h, __nv_bfloat16& l) {
    h = __float2bfloat16_rn(v);
    l = __float2bfloat16_rn(v - __bfloat162float(h));
}
__device__ __forceinline__ void store_pair(__nv_bfloat16* p, __nv_bfloat16 a, __nv_bfloat16 b) {
    *(__nv_bfloat162*)p = __halves2bfloat162(a, b);
}
__device__ __forceinline__ void hmma(float* c, const uint32_t* a, const uint32_t* b) {
    asm volatile(
        "mma.sync.aligned.m16n8k16.row.col.f32.bf16.bf16.f32 "
        "{%0,%1,%2,%3}, {%4,%5,%6,%7}, {%8,%9}, {%0,%1,%2,%3};"
        : "+f"(c[0]), "+f"(c[1]), "+f"(c[2]), "+f"(c[3])
        : "r"(a[0]), "r"(a[1]), "r"(a[2]), "r"(a[3]), "r"(b[0]), "r"(b[1]));
}
__device__ __forceinline__ void ldsm4(uint32_t* r, uint32_t addr) {
    asm volatile("ldmatrix.sync.aligned.m8n8.x4.shared.b16 {%0,%1,%2,%3}, [%4];"
                 : "=r"(r[0]), "=r"(r[1]), "=r"(r[2]), "=r"(r[3]) : "r"(addr));
}

// ===========================================================================
// Single weight-prep kernel: transpose+split all weights, build merged
// off+attn weight [384][256] and merged bias [384].
// ===========================================================================
#define SEG0 65536            // W_val  [256][256]
#define SEG1 (SEG0 + 65536)   // W_off  [256][256] -> w_oa rows 0-255
#define SEG2 (SEG1 + 32768)   // W_attn [256][128] -> w_oa rows 256-383
#define SEG3 (SEG2 + 65536)   // W_out  [256][256]
#define SEG4 (SEG3 + 262144)  // W1     [256][1024]
#define SEG5 (SEG4 + 262144)  // W2     [1024][256]
#define SEG6 (SEG5 + 384)     // bias concat
#define PREP_TOT SEG6

__global__ void __launch_bounds__(256) prep_kernel(
    const float* __restrict__ Wv, const float* __restrict__ Wo,
    const float* __restrict__ Wa, const float* __restrict__ Wu,
    const float* __restrict__ W1, const float* __restrict__ W2,
    const float* __restrict__ boff, const float* __restrict__ battn)
{
    int i = blockIdx.x * 256 + threadIdx.x;
    if (i >= PREP_TOT) return;
    __nv_bfloat16 h, l;
    if (i < SEG0) {
        int k = i >> 8, n = i & 255;
        splitf(Wv[i], h, l);
        w_v_h[n * DD + k] = h; w_v_l[n * DD + k] = l;
    } else if (i < SEG1) {
        int j = i - SEG0;
        int k = j >> 8, n = j & 255;
        splitf(Wo[j], h, l);
        w_oa_h[n * DD + k] = h; w_oa_l[n * DD + k] = l;
    } else if (i < SEG2) {
        int j = i - SEG1;
        int k = j >> 7, n = j & 127;
        splitf(Wa[j], h, l);
        w_oa_h[(256 + n) * DD + k] = h; w_oa_l[(256 + n) * DD + k] = l;
    } else if (i < SEG3) {
        int j = i - SEG2;
        int k = j >> 8, n = j & 255;
        splitf(Wu[j], h, l);
        w_u_h[n * DD + k] = h; w_u_l[n * DD + k] = l;
    } else if (i < SEG4) {
        int j = i - SEG3;
        int k = j >> 10, n = j & 1023;   // [256][1024]
        splitf(W1[j], h, l);
        w_1_h[n * DD + k] = h; w_1_l[n * DD + k] = l;
    } else if (i < SEG5) {
        int j = i - SEG4;
        int k = j >> 8, n = j & 255;     // [1024][256]
        splitf(W2[j], h, l);
        w_2_h[n * FFF + k] = h; w_2_l[n * FFF + k] = l;
    } else {
        int j = i - SEG5;
        g_boa[j] = (j < 256) ? boff[j] : battn[j - 256];
    }
}

// ===========================================================================
// query / query+pos split
// ===========================================================================
__global__ void __launch_bounds__(256) splitq_kernel(
    const float* __restrict__ Q, const float* __restrict__ P)
{
    int i = blockIdx.x * 256 + threadIdx.x;
    if (i >= MM * (DD / 4)) return;
    float4 q = ((const float4*)Q)[i];
    float4 p = ((const float4*)P)[i];
    size_t o = (size_t)i * 4;
    __nv_bfloat16 h0, l0, h1, l1, h2, l2, h3, l3;
    splitf(q.x, h0, l0); splitf(q.y, h1, l1); splitf(q.z, h2, l2); splitf(q.w, h3, l3);
    store_pair(g_qh + o, h0, h1); store_pair(g_qh + o + 2, h2, h3);
    store_pair(g_ql + o, l0, l1); store_pair(g_ql + o + 2, l2, l3);
    float4 s = make_float4(q.x + p.x, q.y + p.y, q.z + p.z, q.w + p.w);
    splitf(s.x, h0, l0); splitf(s.y, h1, l1); splitf(s.z, h2, l2); splitf(s.w, h3, l3);
    store_pair(g_qph + o, h0, h1); store_pair(g_qph + o + 2, h2, h3);
    store_pair(g_qpl + o, l0, l1); store_pair(g_qpl + o + 2, l2, l3);
}

// ===========================================================================
// mma.sync bf16-split GEMM (ldmatrix fragments): C = A @ B^T + bias
//   MODE 0: f32 +bias -> Cf[M,N]
//   MODE 1: f32 +bias -> value layout (b,h,s,hd)
//   MODE 2: relu(.+bias) -> bf16 hi/lo split Chi/Clo
//   MODE 3: merged off/attn: c<256 -> Cf (stride 256), else Cf2 (stride 128)
// CTA tile 128x128, BK=32, 8 warps (4x2), warp tile 32x64, 2-stage cp.async.
// ===========================================================================
#define KSTR 40                         // padded row stride (bf16 elems)
#define TEN_B (128 * KSTR * 2)          // 10240
#define BUF_B (4 * TEN_B)               // 40960
#define GEMM_SMEM (2 * BUF_B)           // 81920

template <int MODE>
__global__ void __launch_bounds__(256) mma_gemm(
    const __nv_bfloat16* __restrict__ Ah, const __nv_bfloat16* __restrict__ Al,
    const __nv_bfloat16* __restrict__ Bh, const __nv_bfloat16* __restrict__ Bl,
    const float* __restrict__ bias,
    float* __restrict__ Cf, float* __restrict__ Cf2,
    __nv_bfloat16* __restrict__ Chi, __nv_bfloat16* __restrict__ Clo,
    int Mdim, int Ndim, int Kdim)
{
    extern __shared__ char smem[];
    const uint32_t sb = smem_u32(smem);
    const int tid = threadIdx.x;
    const int wid = tid >> 5;
    const int lane = tid & 31;
    const int wm = wid & 3;
    const int wn = wid >> 2;
    const int m0 = blockIdx.y * 128;
    const int n0 = blockIdx.x * 128;
    const int NC = Kdim >> 5;

    const int l4 = lane >> 2;
    const int t4 = lane & 3;

    // per-lane invariant ldmatrix byte offsets
    const uint32_t a_off = ((uint32_t)(wm * 32 + (lane & 15)) * KSTR + (lane >> 4) * 8) * 2;
    const uint32_t b_off = ((uint32_t)(wn * 64 + (lane >> 4) * 8 + (lane & 7)) * KSTR +
                            ((lane >> 3) & 1) * 8) * 2;

    float acc[2][8][4];
#pragma unroll
    for (int i = 0; i < 2; i++)
#pragma unroll
        for (int j = 0; j < 8; j++)
#pragma unroll
            for (int q = 0; q < 4; q++) acc[i][j][q] = 0.f;

    auto load_chunk = [&](int kc) {
        const int b = kc & 1;
        const int k0 = kc * 32;
        const uint32_t bufb = sb + b * BUF_B;
#pragma unroll
        for (int t = 0; t < 4; t++) {
            const __nv_bfloat16* src = (t == 0) ? Ah : (t == 1) ? Al : (t == 2) ? Bh : Bl;
            const int rb = (t < 2) ? m0 : n0;
#pragma unroll
            for (int e = 0; e < 2; e++) {
                int u = tid + e * 256;
                int r = u >> 2;
                int g = u & 3;
                int gr = rb + r;
                if (t < 2) { if (gr >= Mdim) gr = Mdim - 1; }
                cp16(bufb + (uint32_t)t * TEN_B + (uint32_t)(r * KSTR + g * 8) * 2,
                     src + (size_t)gr * Kdim + k0 + g * 8);
            }
        }
        cp_commit();
    };

    load_chunk(0);

#pragma unroll 1
    for (int kc = 0; kc < NC; kc++) {
        if (kc + 1 < NC) {
            load_chunk(kc + 1);
            asm volatile("cp.async.wait_group 1;" ::: "memory");
        } else {
            asm volatile("cp.async.wait_group 0;" ::: "memory");
        }
        __syncthreads();

        const uint32_t buf = sb + (kc & 1) * BUF_B;
        const uint32_t pAh = buf;
        const uint32_t pAl = buf + TEN_B;
        const uint32_t pBh = buf + 2 * TEN_B;
        const uint32_t pBl = buf + 3 * TEN_B;

#pragma unroll
        for (int ks = 0; ks < 2; ks++) {
            const uint32_t kb = ks * 32;   // 16 elems * 2B
            uint32_t afh[2][4], afl[2][4];
            ldsm4(afh[0], pAh + a_off + kb);
            ldsm4(afh[1], pAh + a_off + 16 * KSTR * 2 + kb);
            ldsm4(afl[0], pAl + a_off + kb);
            ldsm4(afl[1], pAl + a_off + 16 * KSTR * 2 + kb);
#pragma unroll
            for (int np = 0; np < 4; np++) {
                const uint32_t bo = b_off + (uint32_t)np * 16 * KSTR * 2 + kb;
                uint32_t bh4[4], bl4[4];
                ldsm4(bh4, pBh + bo);
                ldsm4(bl4, pBl + bo);
#pragma unroll
                for (int mt = 0; mt < 2; mt++) {
                    hmma(acc[mt][np * 2], afh[mt], bh4);
                    hmma(acc[mt][np * 2], afh[mt], bl4);
                    hmma(acc[mt][np * 2], afl[mt], bh4);
                    hmma(acc[mt][np * 2 + 1], afh[mt], bh4 + 2);
                    hmma(acc[mt][np * 2 + 1], afh[mt], bl4 + 2);
                    hmma(acc[mt][np * 2 + 1], afl[mt], bh4 + 2);
                }
            }
        }
        __syncthreads();
    }

    // ---- epilogue from register fragments ----
#pragma unroll
    for (int mt = 0; mt < 2; mt++) {
        int r0 = m0 + wm * 32 + mt * 16 + l4;
#pragma unroll
        for (int half = 0; half < 2; half++) {
            int r = r0 + half * 8;
            if (r >= Mdim) continue;
            int bsel = (r >= SS) ? 1 : 0;
            int s = r - bsel * SS;
#pragma unroll
            for (int nt = 0; nt < 8; nt++) {
                int c = n0 + wn * 64 + nt * 8 + t4 * 2;
                float v0 = acc[mt][nt][half * 2 + 0] + bias[c];
                float v1 = acc[mt][nt][half * 2 + 1] + bias[c + 1];
                if (MODE == 0) {
                    *(float2*)(Cf + (size_t)r * Ndim + c) = make_float2(v0, v1);
                } else if (MODE == 1) {
                    int h = c >> 5, hd = c & 31;
                    *(float2*)(Cf + (((size_t)(bsel * 8 + h)) * SS + s) * 32 + hd) =
                        make_float2(v0, v1);
                } else if (MODE == 3) {
                    if (c < 256)
                        *(float2*)(Cf + (size_t)r * 256 + c) = make_float2(v0, v1);
                    else
                        *(float2*)(Cf2 + (size_t)r * 128 + (c - 256)) = make_float2(v0, v1);
                } else {
                    v0 = fmaxf(v0, 0.f);
                    v1 = fmaxf(v1, 0.f);
                    __nv_bfloat16 h0, l0, h1, l1;
                    splitf(v0, h0, l0); splitf(v1, h1, l1);
                    store_pair(Chi + (size_t)r * Ndim + c, h0, h1);
                    store_pair(Clo + (size_t)r * Ndim + c, l0, l1);
                }
            }
        }
    }
}

// ===========================================================================
// Deformable sampling: 8 lanes per (b,s,h), float4 channels per lane.
// ===========================================================================
__global__ void __launch_bounds__(256) sample_kernel(const float* __restrict__ vr)
{
    const int lvlW[4] = {100, 50, 25, 13};
    const int lvlS[4] = {0, 10000, 12500, 13125};

    int gw = (blockIdx.x * 256 + threadIdx.x) >> 5;
    int lane = threadIdx.x & 31;
    int m = gw >> 1;
    if (m >= MM) return;
    int hq = ((gw & 1) << 2) + (lane >> 3);
    int c0 = (lane & 7) << 2;

    int b = (m >= SS) ? 1 : 0;
    int s = m - b * SS;
    int lq, jj;
    if (s < 10000)      { lq = 0; jj = s; }
    else if (s < 12500) { lq = 1; jj = s - 10000; }
    else if (s < 13125) { lq = 2; jj = s - 12500; }
    else                { lq = 3; jj = s - 13125; }
    int Wq = lvlW[lq];
    int yq = jj / Wq, xq = jj - yq * Wq;
    float vrx = vr[(b * 4 + lq) * 2 + 0];
    float vry = vr[(b * 4 + lq) * 2 + 1];
    float refx = ((float)xq + 0.5f) / (vrx * (float)Wq);
    float refy = ((float)yq + 0.5f) / (vry * (float)Wq);

    const float* attp = g_attn + (size_t)m * 128 + hq * 16;
    float logit[16];
    float mx = -1e30f;
#pragma unroll
    for (int t = 0; t < 4; t++) {
        float4 a4 = *(const float4*)(attp + t * 4);
        logit[t * 4 + 0] = a4.x; logit[t * 4 + 1] = a4.y;
        logit[t * 4 + 2] = a4.z; logit[t * 4 + 3] = a4.w;
    }
#pragma unroll
    for (int t = 0; t < 16; t++) mx = fmaxf(mx, logit[t]);
    float se = 0.f;
#pragma unroll
    for (int t = 0; t < 16; t++) { logit[t] = __expf(logit[t] - mx); se += logit[t]; }
    float inv = 1.f / se;

    const float* offp = g_off + (size_t)m * 256 + hq * 32;
    float ax = 0.f, ay = 0.f, az = 0.f, aw = 0.f;

#pragma unroll
    for (int lvl = 0; lvl < 4; lvl++) {
        const int Wl = lvlW[lvl];
        const float* vplane = g_v + (((size_t)(b * 8 + hq)) * SS + lvlS[lvl]) * 32 + c0;
        float fx = refx * (float)Wl - 0.5f;
        float fy = refy * (float)Wl - 0.5f;
        float4 o0 = *(const float4*)(offp + lvl * 8);
        float4 o1 = *(const float4*)(offp + lvl * 8 + 4);
        float oxs[4] = {o0.x, o0.z, o1.x, o1.z};
        float oys[4] = {o0.y, o0.w, o1.y, o1.w};
#pragma unroll
        for (int p = 0; p < 4; p++) {
            float w = logit[lvl * 4 + p];
            float x = fx + oxs[p];
            float y = fy + oys[p];
            float x0f = floorf(x), y0f = floorf(y);
            float lx = x - x0f, ly = y - y0f;
            int x0 = (int)x0f, y0 = (int)y0f;
            bool x0ok = ((unsigned)x0 < (unsigned)Wl);
            bool x1ok = ((unsigned)(x0 + 1) < (unsigned)Wl);
            float w00 = w * (1.f - lx) * (1.f - ly);
            float w01 = w * lx * (1.f - ly);
            float w10 = w * (1.f - lx) * ly;
            float w11 = w * lx * ly;
            if ((unsigned)y0 < (unsigned)Wl) {
                const float* rp = vplane + (size_t)(y0 * Wl) * 32;
                if (x0ok) {
                    float4 v = *(const float4*)(rp + (size_t)x0 * 32);
                    ax = fmaf(w00, v.x, ax); ay = fmaf(w00, v.y, ay);
                    az = fmaf(w00, v.z, az); aw = fmaf(w00, v.w, aw);
                }
                if (x1ok) {
                    float4 v = *(const float4*)(rp + (size_t)(x0 + 1) * 32);
                    ax = fmaf(w01, v.x, ax); ay = fmaf(w01, v.y, ay);
                    az = fmaf(w01, v.z, az); aw = fmaf(w01, v.w, aw);
                }
            }
            if ((unsigned)(y0 + 1) < (unsigned)Wl) {
                const float* rp = vplane + (size_t)((y0 + 1) * Wl) * 32;
                if (x0ok) {
                    float4 v = *(const float4*)(rp + (size_t)x0 * 32);
                    ax = fmaf(w10, v.x, ax); ay = fmaf(w10, v.y, ay);
                    az = fmaf(w10, v.z, az); aw = fmaf(w10, v.w, aw);
                }
                if (x1ok) {
                    float4 v = *(const float4*)(rp + (size_t)(x0 + 1) * 32);
                    ax = fmaf(w11, v.x, ax); ay = fmaf(w11, v.y, ay);
                    az = fmaf(w11, v.z, az); aw = fmaf(w11, v.w, aw);
                }
            }
        }
    }
    ax *= inv; ay *= inv; az *= inv; aw *= inv;

    size_t ob = (size_t)m * 256 + hq * 32 + c0;
    __nv_bfloat16 h0, l0, h1, l1, h2, l2, h3, l3;
    splitf(ax, h0, l0); splitf(ay, h1, l1); splitf(az, h2, l2); splitf(aw, h3, l3);
    store_pair(g_sh + ob, h0, h1); store_pair(g_sh + ob + 2, h2, h3);
    store_pair(g_sl + ob, l0, l1); store_pair(g_sl + ob + 2, l2, l3);
}

// ===========================================================================
// Row LayerNorm: X = LN(A + R); optionally also bf16 hi/lo split.
// ===========================================================================
template <bool WB>
__global__ void __launch_bounds__(256) ln_kernel(
    const float* __restrict__ A, const float* __restrict__ R,
    const float* __restrict__ gam, const float* __restrict__ bet,
    float* __restrict__ Xf, __nv_bfloat16* __restrict__ Xh,
    __nv_bfloat16* __restrict__ Xl)
{
    int row = blockIdx.x * 8 + (threadIdx.x >> 5);
    if (row >= MM) return;
    int lane = threadIdx.x & 31;
    const float4* pa = (const float4*)(A + (size_t)row * 256);
    const float4* pr = (const float4*)(R + (size_t)row * 256);
    float4 v0 = pa[lane],      r0 = pr[lane];
    float4 v1 = pa[lane + 32], r1 = pr[lane + 32];
    v0.x += r0.x; v0.y += r0.y; v0.z += r0.z; v0.w += r0.w;
    v1.x += r1.x; v1.y += r1.y; v1.z += r1.z; v1.w += r1.w;

    float s = v0.x + v0.y + v0.z + v0.w + v1.x + v1.y + v1.z + v1.w;
#pragma unroll
    for (int d = 1; d < 32; d <<= 1) s += __shfl_xor_sync(0xffffffffu, s, d);
    float mean = s * (1.f / 256.f);
    float vs =
        (v0.x - mean) * (v0.x - mean) + (v0.y - mean) * (v0.y - mean) +
        (v0.z - mean) * (v0.z - mean) + (v0.w - mean) * (v0.w - mean) +
        (v1.x - mean) * (v1.x - mean) + (v1.y - mean) * (v1.y - mean) +
        (v1.z - mean) * (v1.z - mean) + (v1.w - mean) * (v1.w - mean);
#pragma unroll
    for (int d = 1; d < 32; d <<= 1) vs += __shfl_xor_sync(0xffffffffu, vs, d);
    float rstd = rsqrtf(vs * (1.f / 256.f) + 1e-5f);

    float4 g0 = ((const float4*)gam)[lane], g1 = ((const float4*)gam)[lane + 32];
    float4 b0 = ((const float4*)bet)[lane], b1 = ((const float4*)bet)[lane + 32];
    float4 o0, o1;
    o0.x = (v0.x - mean) * rstd * g0.x + b0.x;
    o0.y = (v0.y - mean) * rstd * g0.y + b0.y;
    o0.z = (v0.z - mean) * rstd * g0.z + b0.z;
    o0.w = (v0.w - mean) * rstd * g0.w + b0.w;
    o1.x = (v1.x - mean) * rstd * g1.x + b1.x;
    o1.y = (v1.y - mean) * rstd * g1.y + b1.y;
    o1.z = (v1.z - mean) * rstd * g1.z + b1.z;
    o1.w = (v1.w - mean) * rstd * g1.w + b1.w;
    ((float4*)(Xf + (size_t)row * 256))[lane] = o0;
    ((float4*)(Xf + (size_t)row * 256))[lane + 32] = o1;

    if (WB) {
        size_t ob = (size_t)row * 256 + lane * 4;
        __nv_bfloat16 h0, l0, h1, l1, h2, l2, h3, l3;
        splitf(o0.x, h0, l0); splitf(o0.y, h1, l1); splitf(o0.z, h2, l2); splitf(o0.w, h3, l3);
        store_pair(Xh + ob, h0, h1); store_pair(Xh + ob + 2, h2, h3);
        store_pair(Xl + ob, l0, l1); store_pair(Xl + ob + 2, l2, l3);
        ob += 128;
        splitf(o1.x, h0, l0); splitf(o1.y, h1, l1); splitf(o1.z, h2, l2); splitf(o1.w, h3, l3);
        store_pair(Xh + ob, h0, h1); store_pair(Xh + ob + 2, h2, h3);
        store_pair(Xl + ob, l0, l1); store_pair(Xl + ob + 2, l2, l3);
    }
}

// ===========================================================================
// Launch
// ===========================================================================
extern "C" void kernel_launch(void* const* d_in, const int* in_sizes, int n_in,
                              void* d_out, int out_size)
{
    const float* query  = (const float*)d_in[0];
    const float* qpos   = (const float*)d_in[1];
    const float* vrat   = (const float*)d_in[2];
    const float* W_off  = (const float*)d_in[5];
    const float* b_off  = (const float*)d_in[6];
    const float* W_attn = (const float*)d_in[7];
    const float* b_attn = (const float*)d_in[8];
    const float* W_val  = (const float*)d_in[9];
    const float* b_val  = (const float*)d_in[10];
    const float* W_out  = (const float*)d_in[11];
    const float* b_out  = (const float*)d_in[12];
    const float* ln1g   = (const float*)d_in[13];
    const float* ln1b   = (const float*)d_in[14];
    const float* W1     = (const float*)d_in[15];
    const float* b1     = (const float*)d_in[16];
    const float* W2     = (const float*)d_in[17];
    const float* b2     = (const float*)d_in[18];
    const float* ln2g   = (const float*)d_in[19];
    const float* ln2b   = (const float*)d_in[20];
    float* out = (float*)d_out;

    void *p_qh, *p_ql, *p_qph, *p_qpl, *p_v, *p_off, *p_attn, *p_sh, *p_sl;
    void *p_ao, *p_x, *p_xh, *p_xl, *p_hh, *p_hl, *p_f, *p_boa;
    void *pwvh, *pwvl, *pwoah, *pwoal, *pwuh, *pwul, *pw1h, *pw1l, *pw2h, *pw2l;
    cudaGetSymbolAddress(&p_qh, g_qh);   cudaGetSymbolAddress(&p_ql, g_ql);
    cudaGetSymbolAddress(&p_qph, g_qph); cudaGetSymbolAddress(&p_qpl, g_qpl);
    cudaGetSymbolAddress(&p_v, g_v);     cudaGetSymbolAddress(&p_off, g_off);
    cudaGetSymbolAddress(&p_attn, g_attn);
    cudaGetSymbolAddress(&p_sh, g_sh);   cudaGetSymbolAddress(&p_sl, g_sl);
    cudaGetSymbolAddress(&p_ao, g_ao);   cudaGetSymbolAddress(&p_x, g_x);
    cudaGetSymbolAddress(&p_xh, g_xh);   cudaGetSymbolAddress(&p_xl, g_xl);
    cudaGetSymbolAddress(&p_hh, g_hh);   cudaGetSymbolAddress(&p_hl, g_hl);
    cudaGetSymbolAddress(&p_f, g_f);     cudaGetSymbolAddress(&p_boa, g_boa);
    cudaGetSymbolAddress(&pwvh, w_v_h);  cudaGetSymbolAddress(&pwvl, w_v_l);
    cudaGetSymbolAddress(&pwoah, w_oa_h); cudaGetSymbolAddress(&pwoal, w_oa_l);
    cudaGetSymbolAddress(&pwuh, w_u_h);  cudaGetSymbolAddress(&pwul, w_u_l);
    cudaGetSymbolAddress(&pw1h, w_1_h);  cudaGetSymbolAddress(&pw1l, w_1_l);
    cudaGetSymbolAddress(&pw2h, w_2_h);  cudaGetSymbolAddress(&pw2l, w_2_l);

    cudaFuncSetAttribute(mma_gemm<0>, cudaFuncAttributeMaxDynamicSharedMemorySize, GEMM_SMEM);
    cudaFuncSetAttribute(mma_gemm<1>, cudaFuncAttributeMaxDynamicSharedMemorySize, GEMM_SMEM);
    cudaFuncSetAttribute(mma_gemm<2>, cudaFuncAttributeMaxDynamicSharedMemorySize, GEMM_SMEM);
    cudaFuncSetAttribute(mma_gemm<3>, cudaFuncAttributeMaxDynamicSharedMemorySize, GEMM_SMEM);

    // --- prep (weights + bias concat) ---
    prep_kernel<<<(PREP_TOT + 255) / 256, 256>>>(
        W_val, W_off, W_attn, W_out, W1, W2, b_off, b_attn);
    // --- activation split ---
    splitq_kernel<<<(MM * (DD / 4) + 255) / 256, 256>>>(query, qpos);

    const int MT = (MM + 127) / 128;   // 208

    // value projection -> g_v (permuted)
    mma_gemm<1><<<dim3(2, MT), 256, GEMM_SMEM>>>(
        (const __nv_bfloat16*)p_qh, (const __nv_bfloat16*)p_ql,
        (const __nv_bfloat16*)pwvh, (const __nv_bfloat16*)pwvl,
        b_val, (float*)p_v, nullptr, nullptr, nullptr, MM, DD, DD);
    // offsets + attention logits (merged, N=384)
    mma_gemm<3><<<dim3(3, MT), 256, GEMM_SMEM>>>(
        (const __nv_bfloat16*)p_qph, (const __nv_bfloat16*)p_qpl,
        (const __nv_bfloat16*)pwoah, (const __nv_bfloat16*)pwoal,
        (const float*)p_boa, (float*)p_off, (float*)p_attn, nullptr, nullptr,
        MM, 384, DD);
    // sampling
    sample_kernel<<<(MM * 8 + 31) / 32, 256>>>(vrat);
    // out projection -> g_ao
    mma_gemm<0><<<dim3(2, MT), 256, GEMM_SMEM>>>(
        (const __nv_bfloat16*)p_sh, (const __nv_bfloat16*)p_sl,
        (const __nv_bfloat16*)pwuh, (const __nv_bfloat16*)pwul,
        b_out, (float*)p_ao, nullptr, nullptr, nullptr, MM, DD, DD);
    // LN1
    ln_kernel<true><<<(MM + 7) / 8, 256>>>(
        (const float*)p_ao, query, ln1g, ln1b,
        (float*)p_x, (__nv_bfloat16*)p_xh, (__nv_bfloat16*)p_xl);
    // FFN up + relu -> h (bf16 split)
    mma_gemm<2><<<dim3(8, MT), 256, GEMM_SMEM>>>(
        (const __nv_bfloat16*)p_xh, (const __nv_bfloat16*)p_xl,
        (const __nv_bfloat16*)pw1h, (const __nv_bfloat16*)pw1l,
        b1, nullptr, nullptr, (__nv_bfloat16*)p_hh, (__nv_bfloat16*)p_hl, MM, FFF, DD);
    // FFN down -> g_f
    mma_gemm<0><<<dim3(2, MT), 256, GEMM_SMEM>>>(
        (const __nv_bfloat16*)p_hh, (const __nv_bfloat16*)p_hl,
        (const __nv_bfloat16*)pw2h, (const __nv_bfloat16*)pw2l,
        b2, (float*)p_f, nullptr, nullptr, nullptr, MM, DD, FFF);
    // LN2 -> out
    ln_kernel<false><<<(MM + 7) / 8, 256>>>(
        (const float*)p_f, (const float*)p_x, ln2g, ln2b,
        out, nullptr, nullptr);

    (void)in_sizes; (void)n_in; (void)out_size;
}

// round 13
// speedup vs baseline: 2.3449x; 1.0278x over previous
#include <cuda_runtime.h>
#include <cuda_bf16.h>
#include <cuda_fp16.h>
#include <math.h>
#include <stdint.h>

// ---------------- Problem constants ----------------
#define BB 2
#define SS 13294
#define DD 256
#define FFF 1024
#define MM (BB * SS)   // 26588

// ---------------- Scratch (device globals) ----------------
__device__ __nv_bfloat16 g_qh[(size_t)MM * DD], g_ql[(size_t)MM * DD];
__device__ __nv_bfloat16 g_qph[(size_t)MM * DD], g_qpl[(size_t)MM * DD];
__device__ __half g_v[(size_t)MM * DD];          // value tensor, fp16 (b,h,s,hd)
__device__ float g_off[(size_t)MM * DD];
__device__ float g_attn[(size_t)MM * 128];
__device__ __nv_bfloat16 g_sh[(size_t)MM * DD], g_sl[(size_t)MM * DD];
__device__ float g_ao[(size_t)MM * DD];
__device__ float g_x[(size_t)MM * DD];
__device__ __nv_bfloat16 g_xh[(size_t)MM * DD], g_xl[(size_t)MM * DD];
__device__ __nv_bfloat16 g_hh[(size_t)MM * FFF], g_hl[(size_t)MM * FFF];
__device__ float g_f[(size_t)MM * DD];
// weights transposed + split: [N][K] bf16 hi/lo
__device__ __nv_bfloat16 w_v_h[DD * DD],   w_v_l[DD * DD];
__device__ __nv_bfloat16 w_oa_h[384 * DD], w_oa_l[384 * DD];   // off(0-255) + attn(256-383)
__device__ __nv_bfloat16 w_u_h[DD * DD],   w_u_l[DD * DD];
__device__ __nv_bfloat16 w_1_h[FFF * DD],  w_1_l[FFF * DD];
__device__ __nv_bfloat16 w_2_h[DD * FFF],  w_2_l[DD * FFF];
__device__ float g_boa[384];

// ---------------- helpers ----------------
__device__ __forceinline__ uint32_t smem_u32(const void* p) {
    uint32_t a;
    asm("{ .reg .u64 t; cvta.to.shared.u64 t, %1; cvt.u32.u64 %0, t; }"
        : "=r"(a) : "l"(p));
    return a;
}
__device__ __forceinline__ void cp16(uint32_t dst, const void* src) {
    asm volatile("cp.async.cg.shared.global [%0], [%1], 16;"
                 :: "r"(dst), "l"(src) : "memory");
}
__device__ __forceinline__ void cp_commit() {
    asm volatile("cp.async.commit_group;" ::: "memory");
}
__device__ __forceinline__ void splitf(float v, __nv_bfloat16& h, __nv_bfloat16& l) {
    h = __float2bfloat16_rn(v);
    l = __float2bfloat16_rn(v - __bfloat162float(h));
}
__device__ __forceinline__ void store_pair(__nv_bfloat16* p, __nv_bfloat16 a, __nv_bfloat16 b) {
    *(__nv_bfloat162*)p = __halves2bfloat162(a, b);
}
__device__ __forceinline__ void hmma(float* c, const uint32_t* a, const uint32_t* b) {
    asm volatile(
        "mma.sync.aligned.m16n8k16.row.col.f32.bf16.bf16.f32 "
        "{%0,%1,%2,%3}, {%4,%5,%6,%7}, {%8,%9}, {%0,%1,%2,%3};"
        : "+f"(c[0]), "+f"(c[1]), "+f"(c[2]), "+f"(c[3])
        : "r"(a[0]), "r"(a[1]), "r"(a[2]), "r"(a[3]), "r"(b[0]), "r"(b[1]));
}
__device__ __forceinline__ void ldsm4(uint32_t* r, uint32_t addr) {
    asm volatile("ldmatrix.sync.aligned.m8n8.x4.shared.b16 {%0,%1,%2,%3}, [%4];"
                 : "=r"(r[0]), "=r"(r[1]), "=r"(r[2]), "=r"(r[3]) : "r"(addr));
}

// ===========================================================================
// Single weight-prep kernel
// ===========================================================================
#define SEG0 65536            // W_val  [256][256]
#define SEG1 (SEG0 + 65536)   // W_off  [256][256] -> w_oa rows 0-255
#define SEG2 (SEG1 + 32768)   // W_attn [256][128] -> w_oa rows 256-383
#define SEG3 (SEG2 + 65536)   // W_out  [256][256]
#define SEG4 (SEG3 + 262144)  // W1     [256][1024]
#define SEG5 (SEG4 + 262144)  // W2     [1024][256]
#define SEG6 (SEG5 + 384)     // bias concat
#define PREP_TOT SEG6

__global__ void __launch_bounds__(256) prep_kernel(
    const float* __restrict__ Wv, const float* __restrict__ Wo,
    const float* __restrict__ Wa, const float* __restrict__ Wu,
    const float* __restrict__ W1, const float* __restrict__ W2,
    const float* __restrict__ boff, const float* __restrict__ battn)
{
    int i = blockIdx.x * 256 + threadIdx.x;
    if (i >= PREP_TOT) return;
    __nv_bfloat16 h, l;
    if (i < SEG0) {
        int k = i >> 8, n = i & 255;
        splitf(Wv[i], h, l);
        w_v_h[n * DD + k] = h; w_v_l[n * DD + k] = l;
    } else if (i < SEG1) {
        int j = i - SEG0;
        int k = j >> 8, n = j & 255;
        splitf(Wo[j], h, l);
        w_oa_h[n * DD + k] = h; w_oa_l[n * DD + k] = l;
    } else if (i < SEG2) {
        int j = i - SEG1;
        int k = j >> 7, n = j & 127;
        splitf(Wa[j], h, l);
        w_oa_h[(256 + n) * DD + k] = h; w_oa_l[(256 + n) * DD + k] = l;
    } else if (i < SEG3) {
        int j = i - SEG2;
        int k = j >> 8, n = j & 255;
        splitf(Wu[j], h, l);
        w_u_h[n * DD + k] = h; w_u_l[n * DD + k] = l;
    } else if (i < SEG4) {
        int j = i - SEG3;
        int k = j >> 10, n = j & 1023;   // [256][1024]
        splitf(W1[j], h, l);
        w_1_h[n * DD + k] = h; w_1_l[n * DD + k] = l;
    } else if (i < SEG5) {
        int j = i - SEG4;
        int k = j >> 8, n = j & 255;     // [1024][256]
        splitf(W2[j], h, l);
        w_2_h[n * FFF + k] = h; w_2_l[n * FFF + k] = l;
    } else {
        int j = i - SEG5;
        g_boa[j] = (j < 256) ? boff[j] : battn[j - 256];
    }
}

// ===========================================================================
// query / query+pos split
// ===========================================================================
__global__ void __launch_bounds__(256) splitq_kernel(
    const float* __restrict__ Q, const float* __restrict__ P)
{
    int i = blockIdx.x * 256 + threadIdx.x;
    if (i >= MM * (DD / 4)) return;
    float4 q = ((const float4*)Q)[i];
    float4 p = ((const float4*)P)[i];
    size_t o = (size_t)i * 4;
    __nv_bfloat16 h0, l0, h1, l1, h2, l2, h3, l3;
    splitf(q.x, h0, l0); splitf(q.y, h1, l1); splitf(q.z, h2, l2); splitf(q.w, h3, l3);
    store_pair(g_qh + o, h0, h1); store_pair(g_qh + o + 2, h2, h3);
    store_pair(g_ql + o, l0, l1); store_pair(g_ql + o + 2, l2, l3);
    float4 s = make_float4(q.x + p.x, q.y + p.y, q.z + p.z, q.w + p.w);
    splitf(s.x, h0, l0); splitf(s.y, h1, l1); splitf(s.z, h2, l2); splitf(s.w, h3, l3);
    store_pair(g_qph + o, h0, h1); store_pair(g_qph + o + 2, h2, h3);
    store_pair(g_qpl + o, l0, l1); store_pair(g_qpl + o + 2, l2, l3);
}

// ===========================================================================
// mma.sync bf16-split GEMM (ldmatrix fragments): C = A @ B^T + bias
//   MODE 0: f32 +bias -> Cf[M,N]
//   MODE 1: fp16 +bias -> value layout (b,h,s,hd)
//   MODE 2: relu(.+bias) -> bf16 hi/lo split Chi/Clo
//   MODE 3: merged off/attn: c<256 -> Cf (stride 256), else Cf2 (stride 128)
// CTA tile 128x128, BK=32, 8 warps (4x2), warp tile 32x64.
// 2-stage cp.async, ONE __syncthreads per chunk (load issued post-sync into
// the buffer all warps provably finished last iteration).
// ===========================================================================
#define KSTR 40                         // padded row stride (bf16 elems)
#define TEN_B (128 * KSTR * 2)          // 10240
#define BUF_B (4 * TEN_B)               // 40960
#define GEMM_SMEM (2 * BUF_B)           // 81920

template <int MODE>
__global__ void __launch_bounds__(256) mma_gemm(
    const __nv_bfloat16* __restrict__ Ah, const __nv_bfloat16* __restrict__ Al,
    const __nv_bfloat16* __restrict__ Bh, const __nv_bfloat16* __restrict__ Bl,
    const float* __restrict__ bias,
    float* __restrict__ Cf, float* __restrict__ Cf2,
    __nv_bfloat16* __restrict__ Chi, __nv_bfloat16* __restrict__ Clo,
    __half* __restrict__ Ch,
    int Mdim, int Ndim, int Kdim)
{
    extern __shared__ char smem[];
    const uint32_t sb = smem_u32(smem);
    const int tid = threadIdx.x;
    const int wid = tid >> 5;
    const int lane = tid & 31;
    const int wm = wid & 3;
    const int wn = wid >> 2;
    const int m0 = blockIdx.y * 128;
    const int n0 = blockIdx.x * 128;
    const int NC = Kdim >> 5;

    const int l4 = lane >> 2;
    const int t4 = lane & 3;

    // per-lane invariant ldmatrix byte offsets
    const uint32_t a_off = ((uint32_t)(wm * 32 + (lane & 15)) * KSTR + (lane >> 4) * 8) * 2;
    const uint32_t b_off = ((uint32_t)(wn * 64 + (lane >> 4) * 8 + (lane & 7)) * KSTR +
                            ((lane >> 3) & 1) * 8) * 2;

    float acc[2][8][4];
#pragma unroll
    for (int i = 0; i < 2; i++)
#pragma unroll
        for (int j = 0; j < 8; j++)
#pragma unroll
            for (int q = 0; q < 4; q++) acc[i][j][q] = 0.f;

    auto load_chunk = [&](int kc) {
        const int b = kc & 1;
        const int k0 = kc * 32;
        const uint32_t bufb = sb + b * BUF_B;
#pragma unroll
        for (int t = 0; t < 4; t++) {
            const __nv_bfloat16* src = (t == 0) ? Ah : (t == 1) ? Al : (t == 2) ? Bh : Bl;
            const int rb = (t < 2) ? m0 : n0;
#pragma unroll
            for (int e = 0; e < 2; e++) {
                int u = tid + e * 256;
                int r = u >> 2;
                int g = u & 3;
                int gr = rb + r;
                if (t < 2) { if (gr >= Mdim) gr = Mdim - 1; }
                cp16(bufb + (uint32_t)t * TEN_B + (uint32_t)(r * KSTR + g * 8) * 2,
                     src + (size_t)gr * Kdim + k0 + g * 8);
            }
        }
        cp_commit();
    };

    load_chunk(0);

#pragma unroll 1
    for (int kc = 0; kc < NC; kc++) {
        asm volatile("cp.async.wait_group 0;" ::: "memory");
        __syncthreads();
        // Safe: buffer (kc+1)&1 was last read in iteration kc-1; the barrier
        // above guarantees every warp finished that compute.
        if (kc + 1 < NC) load_chunk(kc + 1);

        const uint32_t buf = sb + (kc & 1) * BUF_B;
        const uint32_t pAh = buf;
        const uint32_t pAl = buf + TEN_B;
        const uint32_t pBh = buf + 2 * TEN_B;
        const uint32_t pBl = buf + 3 * TEN_B;

#pragma unroll
        for (int ks = 0; ks < 2; ks++) {
            const uint32_t kb = ks * 32;   // 16 elems * 2B
            uint32_t afh[2][4], afl[2][4];
            ldsm4(afh[0], pAh + a_off + kb);
            ldsm4(afh[1], pAh + a_off + 16 * KSTR * 2 + kb);
            ldsm4(afl[0], pAl + a_off + kb);
            ldsm4(afl[1], pAl + a_off + 16 * KSTR * 2 + kb);
#pragma unroll
            for (int np = 0; np < 4; np++) {
                const uint32_t bo = b_off + (uint32_t)np * 16 * KSTR * 2 + kb;
                uint32_t bh4[4], bl4[4];
                ldsm4(bh4, pBh + bo);
                ldsm4(bl4, pBl + bo);
#pragma unroll
                for (int mt = 0; mt < 2; mt++) {
                    hmma(acc[mt][np * 2], afh[mt], bh4);
                    hmma(acc[mt][np * 2], afh[mt], bl4);
                    hmma(acc[mt][np * 2], afl[mt], bh4);
                    hmma(acc[mt][np * 2 + 1], afh[mt], bh4 + 2);
                    hmma(acc[mt][np * 2 + 1], afh[mt], bl4 + 2);
                    hmma(acc[mt][np * 2 + 1], afl[mt], bh4 + 2);
                }
            }
        }
    }

    // ---- epilogue from register fragments ----
#pragma unroll
    for (int mt = 0; mt < 2; mt++) {
        int r0 = m0 + wm * 32 + mt * 16 + l4;
#pragma unroll
        for (int half = 0; half < 2; half++) {
            int r = r0 + half * 8;
            if (r >= Mdim) continue;
            int bsel = (r >= SS) ? 1 : 0;
            int s = r - bsel * SS;
#pragma unroll
            for (int nt = 0; nt < 8; nt++) {
                int c = n0 + wn * 64 + nt * 8 + t4 * 2;
                float v0 = acc[mt][nt][half * 2 + 0] + bias[c];
                float v1 = acc[mt][nt][half * 2 + 1] + bias[c + 1];
                if (MODE == 0) {
                    *(float2*)(Cf + (size_t)r * Ndim + c) = make_float2(v0, v1);
                } else if (MODE == 1) {
                    int h = c >> 5, hd = c & 31;
                    *(__half2*)(Ch + (((size_t)(bsel * 8 + h)) * SS + s) * 32 + hd) =
                        __floats2half2_rn(v0, v1);
                } else if (MODE == 3) {
                    if (c < 256)
                        *(float2*)(Cf + (size_t)r * 256 + c) = make_float2(v0, v1);
                    else
                        *(float2*)(Cf2 + (size_t)r * 128 + (c - 256)) = make_float2(v0, v1);
                } else {
                    v0 = fmaxf(v0, 0.f);
                    v1 = fmaxf(v1, 0.f);
                    __nv_bfloat16 h0, l0, h1, l1;
                    splitf(v0, h0, l0); splitf(v1, h1, l1);
                    store_pair(Chi + (size_t)r * Ndim + c, h0, h1);
                    store_pair(Clo + (size_t)r * Ndim + c, l0, l1);
                }
            }
        }
    }
}

// ===========================================================================
// Deformable sampling: 8 lanes per (b,s,h), 4 fp16 channels per lane (uint2).
// ===========================================================================
__global__ void __launch_bounds__(256) sample_kernel(const float* __restrict__ vr)
{
    const int lvlW[4] = {100, 50, 25, 13};
    const int lvlS[4] = {0, 10000, 12500, 13125};

    int gw = (blockIdx.x * 256 + threadIdx.x) >> 5;
    int lane = threadIdx.x & 31;
    int m = gw >> 1;
    if (m >= MM) return;
    int hq = ((gw & 1) << 2) + (lane >> 3);
    int c0 = (lane & 7) << 2;

    int b = (m >= SS) ? 1 : 0;
    int s = m - b * SS;
    int lq, jj;
    if (s < 10000)      { lq = 0; jj = s; }
    else if (s < 12500) { lq = 1; jj = s - 10000; }
    else if (s < 13125) { lq = 2; jj = s - 12500; }
    else                { lq = 3; jj = s - 13125; }
    int Wq = lvlW[lq];
    int yq = jj / Wq, xq = jj - yq * Wq;
    float vrx = vr[(b * 4 + lq) * 2 + 0];
    float vry = vr[(b * 4 + lq) * 2 + 1];
    float refx = ((float)xq + 0.5f) / (vrx * (float)Wq);
    float refy = ((float)yq + 0.5f) / (vry * (float)Wq);

    const float* attp = g_attn + (size_t)m * 128 + hq * 16;
    float logit[16];
    float mx = -1e30f;
#pragma unroll
    for (int t = 0; t < 4; t++) {
        float4 a4 = *(const float4*)(attp + t * 4);
        logit[t * 4 + 0] = a4.x; logit[t * 4 + 1] = a4.y;
        logit[t * 4 + 2] = a4.z; logit[t * 4 + 3] = a4.w;
    }
#pragma unroll
    for (int t = 0; t < 16; t++) mx = fmaxf(mx, logit[t]);
    float se = 0.f;
#pragma unroll
    for (int t = 0; t < 16; t++) { logit[t] = __expf(logit[t] - mx); se += logit[t]; }
    float inv = 1.f / se;

    const float* offp = g_off + (size_t)m * 256 + hq * 32;
    float ax = 0.f, ay = 0.f, az = 0.f, aw = 0.f;

#pragma unroll
    for (int lvl = 0; lvl < 4; lvl++) {
        const int Wl = lvlW[lvl];
        const __half* vplane = g_v + (((size_t)(b * 8 + hq)) * SS + lvlS[lvl]) * 32 + c0;
        float fx = refx * (float)Wl - 0.5f;
        float fy = refy * (float)Wl - 0.5f;
        float4 o0 = *(const float4*)(offp + lvl * 8);
        float4 o1 = *(const float4*)(offp + lvl * 8 + 4);
        float oxs[4] = {o0.x, o0.z, o1.x, o1.z};
        float oys[4] = {o0.y, o0.w, o1.y, o1.w};
#pragma unroll
        for (int p = 0; p < 4; p++) {
            float w = logit[lvl * 4 + p];
            float x = fx + oxs[p];
            float y = fy + oys[p];
            float x0f = floorf(x), y0f = floorf(y);
            float lx = x - x0f, ly = y - y0f;
            int x0 = (int)x0f, y0 = (int)y0f;
            bool x0ok = ((unsigned)x0 < (unsigned)Wl);
            bool x1ok = ((unsigned)(x0 + 1) < (unsigned)Wl);
            float w00 = w * (1.f - lx) * (1.f - ly);
            float w01 = w * lx * (1.f - ly);
            float w10 = w * (1.f - lx) * ly;
            float w11 = w * lx * ly;
#define SAMPLE_CORNER(wgt, pix)                                           \
            {                                                             \
                uint2 u = *(const uint2*)(vplane + (size_t)(pix) * 32);   \
                float2 f0 = __half22float2(*(__half2*)&u.x);              \
                float2 f1 = __half22float2(*(__half2*)&u.y);              \
                ax = fmaf(wgt, f0.x, ax); ay = fmaf(wgt, f0.y, ay);       \
                az = fmaf(wgt, f1.x, az); aw = fmaf(wgt, f1.y, aw);       \
            }
            if ((unsigned)y0 < (unsigned)Wl) {
                int rbase = y0 * Wl;
                if (x0ok) SAMPLE_CORNER(w00, rbase + x0);
                if (x1ok) SAMPLE_CORNER(w01, rbase + x0 + 1);
            }
            if ((unsigned)(y0 + 1) < (unsigned)Wl) {
                int rbase = (y0 + 1) * Wl;
                if (x0ok) SAMPLE_CORNER(w10, rbase + x0);
                if (x1ok) SAMPLE_CORNER(w11, rbase + x0 + 1);
            }
#undef SAMPLE_CORNER
        }
    }
    ax *= inv; ay *= inv; az *= inv; aw *= inv;

    size_t ob = (size_t)m * 256 + hq * 32 + c0;
    __nv_bfloat16 h0, l0, h1, l1, h2, l2, h3, l3;
    splitf(ax, h0, l0); splitf(ay, h1, l1); splitf(az, h2, l2); splitf(aw, h3, l3);
    store_pair(g_sh + ob, h0, h1); store_pair(g_sh + ob + 2, h2, h3);
    store_pair(g_sl + ob, l0, l1); store_pair(g_sl + ob + 2, l2, l3);
}

// ===========================================================================
// Row LayerNorm: X = LN(A + R); optionally also bf16 hi/lo split.
// ===========================================================================
template <bool WB>
__global__ void __launch_bounds__(256) ln_kernel(
    const float* __restrict__ A, const float* __restrict__ R,
    const float* __restrict__ gam, const float* __restrict__ bet,
    float* __restrict__ Xf, __nv_bfloat16* __restrict__ Xh,
    __nv_bfloat16* __restrict__ Xl)
{
    int row = blockIdx.x * 8 + (threadIdx.x >> 5);
    if (row >= MM) return;
    int lane = threadIdx.x & 31;
    const float4* pa = (const float4*)(A + (size_t)row * 256);
    const float4* pr = (const float4*)(R + (size_t)row * 256);
    float4 v0 = pa[lane],      r0 = pr[lane];
    float4 v1 = pa[lane + 32], r1 = pr[lane + 32];
    v0.x += r0.x; v0.y += r0.y; v0.z += r0.z; v0.w += r0.w;
    v1.x += r1.x; v1.y += r1.y; v1.z += r1.z; v1.w += r1.w;

    float s = v0.x + v0.y + v0.z + v0.w + v1.x + v1.y + v1.z + v1.w;
#pragma unroll
    for (int d = 1; d < 32; d <<= 1) s += __shfl_xor_sync(0xffffffffu, s, d);
    float mean = s * (1.f / 256.f);
    float vs =
        (v0.x - mean) * (v0.x - mean) + (v0.y - mean) * (v0.y - mean) +
        (v0.z - mean) * (v0.z - mean) + (v0.w - mean) * (v0.w - mean) +
        (v1.x - mean) * (v1.x - mean) + (v1.y - mean) * (v1.y - mean) +
        (v1.z - mean) * (v1.z - mean) + (v1.w - mean) * (v1.w - mean);
#pragma unroll
    for (int d = 1; d < 32; d <<= 1) vs += __shfl_xor_sync(0xffffffffu, vs, d);
    float rstd = rsqrtf(vs * (1.f / 256.f) + 1e-5f);

    float4 g0 = ((const float4*)gam)[lane], g1 = ((const float4*)gam)[lane + 32];
    float4 b0 = ((const float4*)bet)[lane], b1 = ((const float4*)bet)[lane + 32];
    float4 o0, o1;
    o0.x = (v0.x - mean) * rstd * g0.x + b0.x;
    o0.y = (v0.y - mean) * rstd * g0.y + b0.y;
    o0.z = (v0.z - mean) * rstd * g0.z + b0.z;
    o0.w = (v0.w - mean) * rstd * g0.w + b0.w;
    o1.x = (v1.x - mean) * rstd * g1.x + b1.x;
    o1.y = (v1.y - mean) * rstd * g1.y + b1.y;
    o1.z = (v1.z - mean) * rstd * g1.z + b1.z;
    o1.w = (v1.w - mean) * rstd * g1.w + b1.w;
    ((float4*)(Xf + (size_t)row * 256))[lane] = o0;
    ((float4*)(Xf + (size_t)row * 256))[lane + 32] = o1;

    if (WB) {
        size_t ob = (size_t)row * 256 + lane * 4;
        __nv_bfloat16 h0, l0, h1, l1, h2, l2, h3, l3;
        splitf(o0.x, h0, l0); splitf(o0.y, h1, l1); splitf(o0.z, h2, l2); splitf(o0.w, h3, l3);
        store_pair(Xh + ob, h0, h1); store_pair(Xh + ob + 2, h2, h3);
        store_pair(Xl + ob, l0, l1); store_pair(Xl + ob + 2, l2, l3);
        ob += 128;
        splitf(o1.x, h0, l0); splitf(o1.y, h1, l1); splitf(o1.z, h2, l2); splitf(o1.w, h3, l3);
        store_pair(Xh + ob, h0, h1); store_pair(Xh + ob + 2, h2, h3);
        store_pair(Xl + ob, l0, l1); store_pair(Xl + ob + 2, l2, l3);
    }
}

// ===========================================================================
// Launch
// ===========================================================================
extern "C" void kernel_launch(void* const* d_in, const int* in_sizes, int n_in,
                              void* d_out, int out_size)
{
    const float* query  = (const float*)d_in[0];
    const float* qpos   = (const float*)d_in[1];
    const float* vrat   = (const float*)d_in[2];
    const float* W_off  = (const float*)d_in[5];
    const float* b_off  = (const float*)d_in[6];
    const float* W_attn = (const float*)d_in[7];
    const float* b_attn = (const float*)d_in[8];
    const float* W_val  = (const float*)d_in[9];
    const float* b_val  = (const float*)d_in[10];
    const float* W_out  = (const float*)d_in[11];
    const float* b_out  = (const float*)d_in[12];
    const float* ln1g   = (const float*)d_in[13];
    const float* ln1b   = (const float*)d_in[14];
    const float* W1     = (const float*)d_in[15];
    const float* b1     = (const float*)d_in[16];
    const float* W2     = (const float*)d_in[17];
    const float* b2     = (const float*)d_in[18];
    const float* ln2g   = (const float*)d_in[19];
    const float* ln2b   = (const float*)d_in[20];
    float* out = (float*)d_out;

    void *p_qh, *p_ql, *p_qph, *p_qpl, *p_v, *p_off, *p_attn, *p_sh, *p_sl;
    void *p_ao, *p_x, *p_xh, *p_xl, *p_hh, *p_hl, *p_f, *p_boa;
    void *pwvh, *pwvl, *pwoah, *pwoal, *pwuh, *pwul, *pw1h, *pw1l, *pw2h, *pw2l;
    cudaGetSymbolAddress(&p_qh, g_qh);   cudaGetSymbolAddress(&p_ql, g_ql);
    cudaGetSymbolAddress(&p_qph, g_qph); cudaGetSymbolAddress(&p_qpl, g_qpl);
    cudaGetSymbolAddress(&p_v, g_v);     cudaGetSymbolAddress(&p_off, g_off);
    cudaGetSymbolAddress(&p_attn, g_attn);
    cudaGetSymbolAddress(&p_sh, g_sh);   cudaGetSymbolAddress(&p_sl, g_sl);
    cudaGetSymbolAddress(&p_ao, g_ao);   cudaGetSymbolAddress(&p_x, g_x);
    cudaGetSymbolAddress(&p_xh, g_xh);   cudaGetSymbolAddress(&p_xl, g_xl);
    cudaGetSymbolAddress(&p_hh, g_hh);   cudaGetSymbolAddress(&p_hl, g_hl);
    cudaGetSymbolAddress(&p_f, g_f);     cudaGetSymbolAddress(&p_boa, g_boa);
    cudaGetSymbolAddress(&pwvh, w_v_h);  cudaGetSymbolAddress(&pwvl, w_v_l);
    cudaGetSymbolAddress(&pwoah, w_oa_h); cudaGetSymbolAddress(&pwoal, w_oa_l);
    cudaGetSymbolAddress(&pwuh, w_u_h);  cudaGetSymbolAddress(&pwul, w_u_l);
    cudaGetSymbolAddress(&pw1h, w_1_h);  cudaGetSymbolAddress(&pw1l, w_1_l);
    cudaGetSymbolAddress(&pw2h, w_2_h);  cudaGetSymbolAddress(&pw2l, w_2_l);

    cudaFuncSetAttribute(mma_gemm<0>, cudaFuncAttributeMaxDynamicSharedMemorySize, GEMM_SMEM);
    cudaFuncSetAttribute(mma_gemm<1>, cudaFuncAttributeMaxDynamicSharedMemorySize, GEMM_SMEM);
    cudaFuncSetAttribute(mma_gemm<2>, cudaFuncAttributeMaxDynamicSharedMemorySize, GEMM_SMEM);
    cudaFuncSetAttribute(mma_gemm<3>, cudaFuncAttributeMaxDynamicSharedMemorySize, GEMM_SMEM);

    // --- prep (weights + bias concat) ---
    prep_kernel<<<(PREP_TOT + 255) / 256, 256>>>(
        W_val, W_off, W_attn, W_out, W1, W2, b_off, b_attn);
    // --- activation split ---
    splitq_kernel<<<(MM * (DD / 4) + 255) / 256, 256>>>(query, qpos);

    const int MT = (MM + 127) / 128;   // 208

    // value projection -> g_v (permuted, fp16)
    mma_gemm<1><<<dim3(2, MT), 256, GEMM_SMEM>>>(
        (const __nv_bfloat16*)p_qh, (const __nv_bfloat16*)p_ql,
        (const __nv_bfloat16*)pwvh, (const __nv_bfloat16*)pwvl,
        b_val, nullptr, nullptr, nullptr, nullptr, (__half*)p_v, MM, DD, DD);
    // offsets + attention logits (merged, N=384)
    mma_gemm<3><<<dim3(3, MT), 256, GEMM_SMEM>>>(
        (const __nv_bfloat16*)p_qph, (const __nv_bfloat16*)p_qpl,
        (const __nv_bfloat16*)pwoah, (const __nv_bfloat16*)pwoal,
        (const float*)p_boa, (float*)p_off, (float*)p_attn, nullptr, nullptr,
        nullptr, MM, 384, DD);
    // sampling
    sample_kernel<<<(MM * 8 + 31) / 32, 256>>>(vrat);
    // out projection -> g_ao
    mma_gemm<0><<<dim3(2, MT), 256, GEMM_SMEM>>>(
        (const __nv_bfloat16*)p_sh, (const __nv_bfloat16*)p_sl,
        (const __nv_bfloat16*)pwuh, (const __nv_bfloat16*)pwul,
        b_out, (float*)p_ao, nullptr, nullptr, nullptr, nullptr, MM, DD, DD);
    // LN1
    ln_kernel<true><<<(MM + 7) / 8, 256>>>(
        (const float*)p_ao, query, ln1g, ln1b,
        (float*)p_x, (__nv_bfloat16*)p_xh, (__nv_bfloat16*)p_xl);
    // FFN up + relu -> h (bf16 split)
    mma_gemm<2><<<dim3(8, MT), 256, GEMM_SMEM>>>(
        (const __nv_bfloat16*)p_xh, (const __nv_bfloat16*)p_xl,
        (const __nv_bfloat16*)pw1h, (const __nv_bfloat16*)pw1l,
        b1, nullptr, nullptr, (__nv_bfloat16*)p_hh, (__nv_bfloat16*)p_hl,
        nullptr, MM, FFF, DD);
    // FFN down -> g_f
    mma_gemm<0><<<dim3(2, MT), 256, GEMM_SMEM>>>(
        (const __nv_bfloat16*)p_hh, (const __nv_bfloat16*)p_hl,
        (const __nv_bfloat16*)pw2h, (const __nv_bfloat16*)pw2l,
        b2, (float*)p_f, nullptr, nullptr, nullptr, nullptr, MM, DD, FFF);
    // LN2 -> out
    ln_kernel<false><<<(MM + 7) / 8, 256>>>(
        (const float*)p_f, (const float*)p_x, ln2g, ln2b,
        out, nullptr, nullptr);

    (void)in_sizes; (void)n_in; (void)out_size;
}

// round 15
// speedup vs baseline: 2.7963x; 1.1925x over previous
#include <cuda_runtime.h>
#include <cuda_bf16.h>
#include <cuda_fp16.h>
#include <math.h>
#include <stdint.h>

// ---------------- Problem constants ----------------
#define BB 2
#define SS 13294
#define DD 256
#define FFF 1024
#define MM (BB * SS)   // 26588

// ---------------- Scratch (device globals) ----------------
__device__ float g_q[(size_t)MM * DD];           // tf32-rounded query
__device__ float g_qp[(size_t)MM * DD];          // tf32-rounded query+pos
__device__ __half g_v[(size_t)MM * DD];          // value tensor fp16 (b,h,s,hd)
__device__ float g_off[(size_t)MM * DD];
__device__ float g_attn[(size_t)MM * 128];
__device__ float g_s[(size_t)MM * DD];           // sampled (tf32-rounded)
__device__ float g_ao[(size_t)MM * DD];
__device__ float g_x[(size_t)MM * DD];           // LN1 out (tf32-rounded)
__device__ float g_h[(size_t)MM * FFF];          // FFN hidden (tf32-rounded)
__device__ float g_f[(size_t)MM * DD];
// weights transposed [N][K] f32, tf32-rounded
__device__ float w_v[DD * DD];
__device__ float w_oa[384 * DD];                  // off(0-255) + attn(256-383)
__device__ float w_u[DD * DD];
__device__ float w_1[FFF * DD];
__device__ float w_2[DD * FFF];
__device__ float g_boa[384];

// ---------------- helpers ----------------
__device__ __forceinline__ uint32_t smem_u32(const void* p) {
    uint32_t a;
    asm("{ .reg .u64 t; cvta.to.shared.u64 t, %1; cvt.u32.u64 %0, t; }"
        : "=r"(a) : "l"(p));
    return a;
}
__device__ __forceinline__ void cp16(uint32_t dst, const void* src) {
    asm volatile("cp.async.cg.shared.global [%0], [%1], 16;"
                 :: "r"(dst), "l"(src) : "memory");
}
__device__ __forceinline__ void cp_commit() {
    asm volatile("cp.async.commit_group;" ::: "memory");
}
__device__ __forceinline__ float tf32r(float v) {
    float r;
    asm("cvt.rna.tf32.f32 %0, %1;" : "=f"(r) : "f"(v));
    return r;
}
__device__ __forceinline__ float4 tf32r4(float4 v) {
    return make_float4(tf32r(v.x), tf32r(v.y), tf32r(v.z), tf32r(v.w));
}
__device__ __forceinline__ void hmma_t32(float* c, const uint32_t* a, const uint32_t* b) {
    asm volatile(
        "mma.sync.aligned.m16n8k8.row.col.f32.tf32.tf32.f32 "
        "{%0,%1,%2,%3}, {%4,%5,%6,%7}, {%8,%9}, {%0,%1,%2,%3};"
        : "+f"(c[0]), "+f"(c[1]), "+f"(c[2]), "+f"(c[3])
        : "r"(a[0]), "r"(a[1]), "r"(a[2]), "r"(a[3]), "r"(b[0]), "r"(b[1]));
}
__device__ __forceinline__ void ldsm4(uint32_t* r, uint32_t addr) {
    asm volatile("ldmatrix.sync.aligned.m8n8.x4.shared.b16 {%0,%1,%2,%3}, [%4];"
                 : "=r"(r[0]), "=r"(r[1]), "=r"(r[2]), "=r"(r[3]) : "r"(addr));
}

// ===========================================================================
// Weight prep: transpose + tf32-round all weights; build merged off+attn.
// ===========================================================================
#define SEG0 65536            // W_val  [256][256]
#define SEG1 (SEG0 + 65536)   // W_off  -> w_oa rows 0-255
#define SEG2 (SEG1 + 32768)   // W_attn -> w_oa rows 256-383
#define SEG3 (SEG2 + 65536)   // W_out
#define SEG4 (SEG3 + 262144)  // W1 [256][1024]
#define SEG5 (SEG4 + 262144)  // W2 [1024][256]
#define SEG6 (SEG5 + 384)     // bias concat
#define PREP_TOT SEG6

__global__ void __launch_bounds__(256) prep_kernel(
    const float* __restrict__ Wv, const float* __restrict__ Wo,
    const float* __restrict__ Wa, const float* __restrict__ Wu,
    const float* __restrict__ W1, const float* __restrict__ W2,
    const float* __restrict__ boff, const float* __restrict__ battn)
{
    int i = blockIdx.x * 256 + threadIdx.x;
    if (i >= PREP_TOT) return;
    if (i < SEG0) {
        int k = i >> 8, n = i & 255;
        w_v[n * DD + k] = tf32r(Wv[i]);
    } else if (i < SEG1) {
        int j = i - SEG0;
        int k = j >> 8, n = j & 255;
        w_oa[n * DD + k] = tf32r(Wo[j]);
    } else if (i < SEG2) {
        int j = i - SEG1;
        int k = j >> 7, n = j & 127;
        w_oa[(256 + n) * DD + k] = tf32r(Wa[j]);
    } else if (i < SEG3) {
        int j = i - SEG2;
        int k = j >> 8, n = j & 255;
        w_u[n * DD + k] = tf32r(Wu[j]);
    } else if (i < SEG4) {
        int j = i - SEG3;
        int k = j >> 10, n = j & 1023;
        w_1[n * DD + k] = tf32r(W1[j]);
    } else if (i < SEG5) {
        int j = i - SEG4;
        int k = j >> 8, n = j & 255;
        w_2[n * FFF + k] = tf32r(W2[j]);
    } else {
        int j = i - SEG5;
        g_boa[j] = (j < 256) ? boff[j] : battn[j - 256];
    }
}

// ===========================================================================
// qprep: g_q = tf32(q), g_qp = tf32(q + pos)
// ===========================================================================
__global__ void __launch_bounds__(256) qprep_kernel(
    const float* __restrict__ Q, const float* __restrict__ P)
{
    int i = blockIdx.x * 256 + threadIdx.x;
    if (i >= MM * (DD / 4)) return;
    float4 q = ((const float4*)Q)[i];
    float4 p = ((const float4*)P)[i];
    ((float4*)g_q)[i] = tf32r4(q);
    ((float4*)g_qp)[i] = tf32r4(make_float4(q.x + p.x, q.y + p.y, q.z + p.z, q.w + p.w));
}

// ===========================================================================
// TF32 mma.sync GEMM: C = A @ B^T + bias  (A[M,K], B[N,K], f32 tf32-rounded)
//   MODE 0: f32 +bias -> Cf[M,N]
//   MODE 1: fp16 +bias -> value layout (b,h,s,hd)
//   MODE 2: tf32(relu(.+bias)) -> f32 Cf
//   MODE 3: merged off/attn: c<256 -> Cf (stride 256), else Cf2 (stride 128)
// CTA tile 128x128, BK=32, 8 warps (4x2), warp tile 32x64.
// SW128-swizzled f32 smem tiles, conflict-free ldmatrix, 2-stage cp.async.
// ===========================================================================
#define TEN_B 16384                     // 128 rows x 128 B (32 f32)
#define STAGE_B (2 * TEN_B)             // A + B = 32768
#define GEMM_SMEM (2 * STAGE_B)         // 65536

template <int MODE>
__global__ void __launch_bounds__(256) mma_gemm(
    const float* __restrict__ A, const float* __restrict__ B,
    const float* __restrict__ bias,
    float* __restrict__ Cf, float* __restrict__ Cf2,
    __half* __restrict__ Ch,
    int Mdim, int Ndim, int Kdim)
{
    extern __shared__ char smem[];
    const uint32_t sb = smem_u32(smem);
    const int tid = threadIdx.x;
    const int wid = tid >> 5;
    const int lane = tid & 31;
    const int wm = wid & 3;
    const int wn = wid >> 2;
    const int m0 = blockIdx.y * 128;
    const int n0 = blockIdx.x * 128;
    const int NC = Kdim >> 5;

    const int l4 = lane >> 2;
    const int t4 = lane & 3;

    // ldmatrix per-lane constants (SW128 swizzle: unit ^= row&7, row&7 == lane&7)
    const uint32_t x7 = lane & 7;
    const uint32_t cA = (lane >> 4) & 1;          // A: col-16B-half
    const uint32_t cB = (lane >> 3) & 1;          // B: col-16B-half
    const uint32_t aBase = (uint32_t)(wm * 32 + (lane & 7) + ((lane >> 3) & 1) * 8) * 128;
    const uint32_t bBase = (uint32_t)(wn * 64 + (lane & 7) + ((lane >> 4) & 1) * 8) * 128
                           + TEN_B;

    float acc[2][8][4];
#pragma unroll
    for (int i = 0; i < 2; i++)
#pragma unroll
        for (int j = 0; j < 8; j++)
#pragma unroll
            for (int q = 0; q < 4; q++) acc[i][j][q] = 0.f;

    auto load_chunk = [&](int kc) {
        const int b = kc & 1;
        const int k0 = kc * 32;
        const uint32_t bufb = sb + b * STAGE_B;
#pragma unroll
        for (int e = 0; e < 4; e++) {
            int u = tid + e * 256;
            int r = u >> 3;
            int g = u & 7;
            uint32_t dsw = (uint32_t)r * 128 + (uint32_t)((g ^ (r & 7)) << 4);
            int gr = m0 + r; if (gr >= Mdim) gr = Mdim - 1;
            cp16(bufb + dsw, A + (size_t)gr * Kdim + k0 + g * 4);
            cp16(bufb + TEN_B + dsw, B + (size_t)(n0 + r) * Kdim + k0 + g * 4);
        }
        cp_commit();
    };

    load_chunk(0);

#pragma unroll 1
    for (int kc = 0; kc < NC; kc++) {
        asm volatile("cp.async.wait_group 0;" ::: "memory");
        __syncthreads();
        if (kc + 1 < NC) load_chunk(kc + 1);

        const uint32_t buf = sb + (kc & 1) * STAGE_B;

#pragma unroll
        for (int k8 = 0; k8 < 4; k8++) {
            const uint32_t ua = ((((uint32_t)(k8 << 1)) | cA) ^ x7) << 4;
            const uint32_t ub = ((((uint32_t)(k8 << 1)) | cB) ^ x7) << 4;
            uint32_t a0[4], a1[4];
            ldsm4(a0, buf + aBase + ua);
            ldsm4(a1, buf + aBase + 2048 + ua);
#pragma unroll
            for (int np = 0; np < 4; np++) {
                uint32_t b4[4];
                ldsm4(b4, buf + bBase + (uint32_t)np * 2048 + ub);
                hmma_t32(acc[0][np * 2],     a0, b4);
                hmma_t32(acc[0][np * 2 + 1], a0, b4 + 2);
                hmma_t32(acc[1][np * 2],     a1, b4);
                hmma_t32(acc[1][np * 2 + 1], a1, b4 + 2);
            }
        }
    }

    // ---- epilogue from register fragments ----
#pragma unroll
    for (int mt = 0; mt < 2; mt++) {
        int r0 = m0 + wm * 32 + mt * 16 + l4;
#pragma unroll
        for (int half = 0; half < 2; half++) {
            int r = r0 + half * 8;
            if (r >= Mdim) continue;
            int bsel = (r >= SS) ? 1 : 0;
            int s = r - bsel * SS;
#pragma unroll
            for (int nt = 0; nt < 8; nt++) {
                int c = n0 + wn * 64 + nt * 8 + t4 * 2;
                float v0 = acc[mt][nt][half * 2 + 0] + bias[c];
                float v1 = acc[mt][nt][half * 2 + 1] + bias[c + 1];
                if (MODE == 0) {
                    *(float2*)(Cf + (size_t)r * Ndim + c) = make_float2(v0, v1);
                } else if (MODE == 1) {
                    int h = c >> 5, hd = c & 31;
                    *(__half2*)(Ch + (((size_t)(bsel * 8 + h)) * SS + s) * 32 + hd) =
                        __floats2half2_rn(v0, v1);
                } else if (MODE == 3) {
                    if (c < 256)
                        *(float2*)(Cf + (size_t)r * 256 + c) = make_float2(v0, v1);
                    else
                        *(float2*)(Cf2 + (size_t)r * 128 + (c - 256)) = make_float2(v0, v1);
                } else {
                    v0 = tf32r(fmaxf(v0, 0.f));
                    v1 = tf32r(fmaxf(v1, 0.f));
                    *(float2*)(Cf + (size_t)r * Ndim + c) = make_float2(v0, v1);
                }
            }
        }
    }
}

// ===========================================================================
// Deformable sampling: 8 lanes per (b,s,h), 4 fp16 channels per lane.
// Output tf32-rounded f32 for the out-projection GEMM.
// ===========================================================================
__global__ void __launch_bounds__(256) sample_kernel(const float* __restrict__ vr)
{
    const int lvlW[4] = {100, 50, 25, 13};
    const int lvlS[4] = {0, 10000, 12500, 13125};

    int gw = (blockIdx.x * 256 + threadIdx.x) >> 5;
    int lane = threadIdx.x & 31;
    int m = gw >> 1;
    if (m >= MM) return;
    int hq = ((gw & 1) << 2) + (lane >> 3);
    int c0 = (lane & 7) << 2;

    int b = (m >= SS) ? 1 : 0;
    int s = m - b * SS;
    int lq, jj;
    if (s < 10000)      { lq = 0; jj = s; }
    else if (s < 12500) { lq = 1; jj = s - 10000; }
    else if (s < 13125) { lq = 2; jj = s - 12500; }
    else                { lq = 3; jj = s - 13125; }
    int Wq = lvlW[lq];
    int yq = jj / Wq, xq = jj - yq * Wq;
    float vrx = vr[(b * 4 + lq) * 2 + 0];
    float vry = vr[(b * 4 + lq) * 2 + 1];
    float refx = ((float)xq + 0.5f) / (vrx * (float)Wq);
    float refy = ((float)yq + 0.5f) / (vry * (float)Wq);

    const float* attp = g_attn + (size_t)m * 128 + hq * 16;
    float logit[16];
    float mx = -1e30f;
#pragma unroll
    for (int t = 0; t < 4; t++) {
        float4 a4 = *(const float4*)(attp + t * 4);
        logit[t * 4 + 0] = a4.x; logit[t * 4 + 1] = a4.y;
        logit[t * 4 + 2] = a4.z; logit[t * 4 + 3] = a4.w;
    }
#pragma unroll
    for (int t = 0; t < 16; t++) mx = fmaxf(mx, logit[t]);
    float se = 0.f;
#pragma unroll
    for (int t = 0; t < 16; t++) { logit[t] = __expf(logit[t] - mx); se += logit[t]; }
    float inv = 1.f / se;

    const float* offp = g_off + (size_t)m * 256 + hq * 32;
    float ax = 0.f, ay = 0.f, az = 0.f, aw = 0.f;

#pragma unroll
    for (int lvl = 0; lvl < 4; lvl++) {
        const int Wl = lvlW[lvl];
        const __half* vplane = g_v + (((size_t)(b * 8 + hq)) * SS + lvlS[lvl]) * 32 + c0;
        float fx = refx * (float)Wl - 0.5f;
        float fy = refy * (float)Wl - 0.5f;
        float4 o0 = *(const float4*)(offp + lvl * 8);
        float4 o1 = *(const float4*)(offp + lvl * 8 + 4);
        float oxs[4] = {o0.x, o0.z, o1.x, o1.z};
        float oys[4] = {o0.y, o0.w, o1.y, o1.w};
#pragma unroll
        for (int p = 0; p < 4; p++) {
            float w = logit[lvl * 4 + p];
            float x = fx + oxs[p];
            float y = fy + oys[p];
            float x0f = floorf(x), y0f = floorf(y);
            float lx = x - x0f, ly = y - y0f;
            int x0 = (int)x0f, y0 = (int)y0f;
            bool x0ok = ((unsigned)x0 < (unsigned)Wl);
            bool x1ok = ((unsigned)(x0 + 1) < (unsigned)Wl);
            float w00 = w * (1.f - lx) * (1.f - ly);
            float w01 = w * lx * (1.f - ly);
            float w10 = w * (1.f - lx) * ly;
            float w11 = w * lx * ly;
#define SAMPLE_CORNER(wgt, pix)                                           \
            {                                                             \
                uint2 u = *(const uint2*)(vplane + (size_t)(pix) * 32);   \
                float2 f0 = __half22float2(*(__half2*)&u.x);              \
                float2 f1 = __half22float2(*(__half2*)&u.y);              \
                ax = fmaf(wgt, f0.x, ax); ay = fmaf(wgt, f0.y, ay);       \
                az = fmaf(wgt, f1.x, az); aw = fmaf(wgt, f1.y, aw);       \
            }
            if ((unsigned)y0 < (unsigned)Wl) {
                int rbase = y0 * Wl;
                if (x0ok) SAMPLE_CORNER(w00, rbase + x0);
                if (x1ok) SAMPLE_CORNER(w01, rbase + x0 + 1);
            }
            if ((unsigned)(y0 + 1) < (unsigned)Wl) {
                int rbase = (y0 + 1) * Wl;
                if (x0ok) SAMPLE_CORNER(w10, rbase + x0);
                if (x1ok) SAMPLE_CORNER(w11, rbase + x0 + 1);
            }
#undef SAMPLE_CORNER
        }
    }
    float4 o = make_float4(tf32r(ax * inv), tf32r(ay * inv),
                           tf32r(az * inv), tf32r(aw * inv));
    *(float4*)(g_s + (size_t)m * 256 + hq * 32 + c0) = o;
}

// ===========================================================================
// Row LayerNorm: X = LN(A + R). ROUND: tf32-round output (GEMM input).
// ===========================================================================
template <bool ROUND>
__global__ void __launch_bounds__(256) ln_kernel(
    const float* __restrict__ A, const float* __restrict__ R,
    const float* __restrict__ gam, const float* __restrict__ bet,
    float* __restrict__ Xf)
{
    int row = blockIdx.x * 8 + (threadIdx.x >> 5);
    if (row >= MM) return;
    int lane = threadIdx.x & 31;
    const float4* pa = (const float4*)(A + (size_t)row * 256);
    const float4* pr = (const float4*)(R + (size_t)row * 256);
    float4 v0 = pa[lane],      r0 = pr[lane];
    float4 v1 = pa[lane + 32], r1 = pr[lane + 32];
    v0.x += r0.x; v0.y += r0.y; v0.z += r0.z; v0.w += r0.w;
    v1.x += r1.x; v1.y += r1.y; v1.z += r1.z; v1.w += r1.w;

    float s = v0.x + v0.y + v0.z + v0.w + v1.x + v1.y + v1.z + v1.w;
#pragma unroll
    for (int d = 1; d < 32; d <<= 1) s += __shfl_xor_sync(0xffffffffu, s, d);
    float mean = s * (1.f / 256.f);
    float vs =
        (v0.x - mean) * (v0.x - mean) + (v0.y - mean) * (v0.y - mean) +
        (v0.z - mean) * (v0.z - mean) + (v0.w - mean) * (v0.w - mean) +
        (v1.x - mean) * (v1.x - mean) + (v1.y - mean) * (v1.y - mean) +
        (v1.z - mean) * (v1.z - mean) + (v1.w - mean) * (v1.w - mean);
#pragma unroll
    for (int d = 1; d < 32; d <<= 1) vs += __shfl_xor_sync(0xffffffffu, vs, d);
    float rstd = rsqrtf(vs * (1.f / 256.f) + 1e-5f);

    float4 g0 = ((const float4*)gam)[lane], g1 = ((const float4*)gam)[lane + 32];
    float4 b0 = ((const float4*)bet)[lane], b1 = ((const float4*)bet)[lane + 32];
    float4 o0, o1;
    o0.x = (v0.x - mean) * rstd * g0.x + b0.x;
    o0.y = (v0.y - mean) * rstd * g0.y + b0.y;
    o0.z = (v0.z - mean) * rstd * g0.z + b0.z;
    o0.w = (v0.w - mean) * rstd * g0.w + b0.w;
    o1.x = (v1.x - mean) * rstd * g1.x + b1.x;
    o1.y = (v1.y - mean) * rstd * g1.y + b1.y;
    o1.z = (v1.z - mean) * rstd * g1.z + b1.z;
    o1.w = (v1.w - mean) * rstd * g1.w + b1.w;
    if (ROUND) { o0 = tf32r4(o0); o1 = tf32r4(o1); }
    ((float4*)(Xf + (size_t)row * 256))[lane] = o0;
    ((float4*)(Xf + (size_t)row * 256))[lane + 32] = o1;
}

// ===========================================================================
// Launch
// ===========================================================================
extern "C" void kernel_launch(void* const* d_in, const int* in_sizes, int n_in,
                              void* d_out, int out_size)
{
    const float* query  = (const float*)d_in[0];
    const float* qpos   = (const float*)d_in[1];
    const float* vrat   = (const float*)d_in[2];
    const float* W_off  = (const float*)d_in[5];
    const float* b_off  = (const float*)d_in[6];
    const float* W_attn = (const float*)d_in[7];
    const float* b_attn = (const float*)d_in[8];
    const float* W_val  = (const float*)d_in[9];
    const float* b_val  = (const float*)d_in[10];
    const float* W_out  = (const float*)d_in[11];
    const float* b_out  = (const float*)d_in[12];
    const float* ln1g   = (const float*)d_in[13];
    const float* ln1b   = (const float*)d_in[14];
    const float* W1     = (const float*)d_in[15];
    const float* b1     = (const float*)d_in[16];
    const float* W2     = (const float*)d_in[17];
    const float* b2     = (const float*)d_in[18];
    const float* ln2g   = (const float*)d_in[19];
    const float* ln2b   = (const float*)d_in[20];
    float* out = (float*)d_out;

    void *p_q, *p_qp, *p_v, *p_off, *p_attn, *p_s, *p_ao, *p_x, *p_h, *p_f, *p_boa;
    void *pwv, *pwoa, *pwu, *pw1, *pw2;
    cudaGetSymbolAddress(&p_q, g_q);     cudaGetSymbolAddress(&p_qp, g_qp);
    cudaGetSymbolAddress(&p_v, g_v);     cudaGetSymbolAddress(&p_off, g_off);
    cudaGetSymbolAddress(&p_attn, g_attn);
    cudaGetSymbolAddress(&p_s, g_s);     cudaGetSymbolAddress(&p_ao, g_ao);
    cudaGetSymbolAddress(&p_x, g_x);     cudaGetSymbolAddress(&p_h, g_h);
    cudaGetSymbolAddress(&p_f, g_f);     cudaGetSymbolAddress(&p_boa, g_boa);
    cudaGetSymbolAddress(&pwv, w_v);     cudaGetSymbolAddress(&pwoa, w_oa);
    cudaGetSymbolAddress(&pwu, w_u);     cudaGetSymbolAddress(&pw1, w_1);
    cudaGetSymbolAddress(&pw2, w_2);

    cudaFuncSetAttribute(mma_gemm<0>, cudaFuncAttributeMaxDynamicSharedMemorySize, GEMM_SMEM);
    cudaFuncSetAttribute(mma_gemm<1>, cudaFuncAttributeMaxDynamicSharedMemorySize, GEMM_SMEM);
    cudaFuncSetAttribute(mma_gemm<2>, cudaFuncAttributeMaxDynamicSharedMemorySize, GEMM_SMEM);
    cudaFuncSetAttribute(mma_gemm<3>, cudaFuncAttributeMaxDynamicSharedMemorySize, GEMM_SMEM);

    // --- prep (weights + bias concat), activation rounding ---
    prep_kernel<<<(PREP_TOT + 255) / 256, 256>>>(
        W_val, W_off, W_attn, W_out, W1, W2, b_off, b_attn);
    qprep_kernel<<<(MM * (DD / 4) + 255) / 256, 256>>>(query, qpos);

    const int MT = (MM + 127) / 128;   // 208

    // value projection -> g_v (permuted, fp16)
    mma_gemm<1><<<dim3(2, MT), 256, GEMM_SMEM>>>(
        (const float*)p_q, (const float*)pwv, b_val,
        nullptr, nullptr, (__half*)p_v, MM, DD, DD);
    // offsets + attention logits (merged, N=384)
    mma_gemm<3><<<dim3(3, MT), 256, GEMM_SMEM>>>(
        (const float*)p_qp, (const float*)pwoa, (const float*)p_boa,
        (float*)p_off, (float*)p_attn, nullptr, MM, 384, DD);
    // sampling -> g_s (tf32-rounded f32)
    sample_kernel<<<(MM * 8 + 31) / 32, 256>>>(vrat);
    // out projection -> g_ao
    mma_gemm<0><<<dim3(2, MT), 256, GEMM_SMEM>>>(
        (const float*)p_s, (const float*)pwu, b_out,
        (float*)p_ao, nullptr, nullptr, MM, DD, DD);
    // LN1 -> g_x (tf32-rounded)
    ln_kernel<true><<<(MM + 7) / 8, 256>>>(
        (const float*)p_ao, query, ln1g, ln1b, (float*)p_x);
    // FFN up + relu -> g_h (tf32-rounded)
    mma_gemm<2><<<dim3(8, MT), 256, GEMM_SMEM>>>(
        (const float*)p_x, (const float*)pw1, b1,
        (float*)p_h, nullptr, nullptr, MM, FFF, DD);
    // FFN down -> g_f
    mma_gemm<0><<<dim3(2, MT), 256, GEMM_SMEM>>>(
        (const float*)p_h, (const float*)pw2, b2,
        (float*)p_f, nullptr, nullptr, MM, DD, FFF);
    // LN2 -> out (exact)
    ln_kernel<false><<<(MM + 7) / 8, 256>>>(
        (const float*)p_f, (const float*)p_x, ln2g, ln2b, out);

    (void)in_sizes; (void)n_in; (void)out_size;
}